// round 9
// baseline (speedup 1.0000x reference)
#include <cuda_runtime.h>
#include <cuda_bf16.h>
#include <math.h>
#include <stdint.h>

typedef unsigned short ush;

#define Bb 256
#define Ll 512
#define Ff 28
#define NBLK 128
#define NTHR 256

#define BSTRIDE 552
#define ASTRIDE 136
#define BBYTES  (2*64*BSTRIDE*2)
#define ACHB    (2*64*ASTRIDE*2)   // 34816

#define OFF_B    0
#define OFF_A    141312
#define OFF_G    210944
#define OFF_WAS  228352
#define OFF_BSUM 229376
#define OFF_CTXA 229632
#define OFF_STM  230528
#define SMEM_SZ  230592

__device__ __align__(16) ush g_wb[32*2*64*BSTRIDE];
__device__ __align__(16) ush g_ab[4*5*2*64*ASTRIDE];   // [mt][chunk5][half][64][136]
__device__ float g_xf[Ll*Bb*Ff];
__device__ float g_ua[Ll*Bb];
__device__ float g_bm[Ll*Bb];
__device__ float g_uab[Bb*Ll];
__device__ float g_bmb[Bb*Ll];
__device__ float g_wapart[Bb*32];
__device__ float g_fcpart[(size_t)Ll*Bb*32];
__device__ float g_stats[Ll*2];
__device__ unsigned g_leaf[8*32];
__device__ unsigned g_root;
__device__ volatile unsigned g_gen;
__device__ unsigned g_mcnt[4*32];
__device__ volatile unsigned g_mgen[4*32];

__device__ __forceinline__ void grid_barrier(int blk){
    __threadfence();
    __syncthreads();
    if(threadIdx.x==0){
        unsigned gen=g_gen;
        if((atomicAdd(&g_leaf[(blk&7)*32],1u)&15u)==15u){
            if((atomicAdd(&g_root,1u)&7u)==7u){ __threadfence(); g_gen=gen+1; }
        }
        while(g_gen==gen){}
        __threadfence();
    }
    __syncthreads();
}
__device__ __forceinline__ void mt_barrier(int mt){
    __threadfence();
    __syncthreads();
    if(threadIdx.x==0){
        unsigned gen=g_mgen[mt*32];
        if((atomicAdd(&g_mcnt[mt*32],1u)&31u)==31u){ __threadfence(); g_mgen[mt*32]=gen+1; }
        while(g_mgen[mt*32]==gen){}
        __threadfence();
    }
    __syncthreads();
}
__device__ __forceinline__ float sigm(float x){ return 1.f/(1.f+__expf(-x)); }
__device__ __forceinline__ int pos4(int km){ return 4*((km&7)>>1)+(km&1)+2*(km>>3); }
__device__ __forceinline__ uint32_t smem_u32(const void* p){
    uint32_t a; asm("{ .reg .u64 t; cvta.to.shared.u64 t, %1; cvt.u32.u64 %0, t; }":"=r"(a):"l"(p)); return a;
}
__device__ __forceinline__ void cpa16(uint32_t s, const void* g){
    asm volatile("cp.async.cg.shared.global [%0], [%1], 16;" :: "r"(s), "l"(g));
}
#define CP_COMMIT() asm volatile("cp.async.commit_group;":::"memory")
#define CP_WAIT(n)  asm volatile("cp.async.wait_group %0;"::"n"(n):"memory")

#define MMA(Cr,A0,A1,A2,A3,B0,B1) \
  asm volatile("mma.sync.aligned.m16n8k16.row.col.f32.bf16.bf16.f32 " \
    "{%0,%1,%2,%3},{%4,%5,%6,%7},{%8,%9},{%0,%1,%2,%3};" \
    : "+f"(Cr[0]),"+f"(Cr[1]),"+f"(Cr[2]),"+f"(Cr[3]) \
    : "r"(A0),"r"(A1),"r"(A2),"r"(A3),"r"(B0),"r"(B1))

__device__ __forceinline__ void bf16split(float v, ush& hi, ush& lo){
    __nv_bfloat16 h=__float2bfloat16(v);
    __nv_bfloat16 l=__float2bfloat16(v-__bfloat162float(h));
    hi=*(ush*)&h; lo=*(ush*)&l;
}

__device__ __forceinline__ void mma_chunk(const ush* smA, const ush* smB,
        int bK, int ktn, int mi, int nig, int lane, float (&C)[4][4]){
    const int r=lane>>2, c4=lane&3;
    const ush* aH = smA + (mi*16+r)*ASTRIDE + c4*4;
    const ush* aL = aH + 64*ASTRIDE;
    const ush* bB = smB + (nig*32+r)*BSTRIDE + bK + c4*4;
    for(int kt=0; kt<ktn; kt++){
        int ka=kt*16;
        uint2 a0=*(const uint2*)(aH+ka);
        uint2 a1=*(const uint2*)(aH+8*ASTRIDE+ka);
        uint2 l0=*(const uint2*)(aL+ka);
        uint2 l1=*(const uint2*)(aL+8*ASTRIDE+ka);
        #pragma unroll
        for(int ni=0; ni<4; ni++){
            const ush* bp = bB + ni*8*BSTRIDE + ka;
            uint2 bh=*(const uint2*)bp;
            uint2 bl=*(const uint2*)(bp+64*BSTRIDE);
            MMA(C[ni], a0.x,a1.x,a0.y,a1.y, bh.x,bh.y);
            MMA(C[ni], a0.x,a1.x,a0.y,a1.y, bl.x,bl.y);
            MMA(C[ni], l0.x,l1.x,l0.y,l1.y, bh.x,bh.y);
        }
    }
}

__global__ void pack_w(const float* __restrict__ whh, const float* __restrict__ wih){
    int o=blockIdx.x*blockDim.x+threadIdx.x;
    if(o>=32*64*544) return;
    int nt=o/(64*544); int rem=o-nt*64*544; int j=rem/544; int k=rem%544;
    int row=(j&3)*512 + nt*16 + (j>>2);
    float v = (k<512) ? whh[(size_t)row*512+k] : ((k-512<Ff)? wih[row*Ff+(k-512)] : 0.f);
    ush hi,lo; bf16split(v,hi,lo);
    int pos=(k&~15) + pos4(k&15);
    size_t base=(size_t)nt*2*64*BSTRIDE;
    g_wb[base + (size_t)j*BSTRIDE + pos]=hi;
    g_wb[base + (size_t)64*BSTRIDE + (size_t)j*BSTRIDE + pos]=lo;
}
__global__ void zero_ab(){
    int i=blockIdx.x*blockDim.x+threadIdx.x;
    int n=(int)(sizeof(g_ab)/16);
    if(i<n) ((uint4*)g_ab)[i]=make_uint4(0,0,0,0);
}

__global__ void prep(const float* __restrict__ x, const float* __restrict__ mask,
                     const float* __restrict__ w1, const float* __restrict__ b1,
                     const float* __restrict__ cw, const float* __restrict__ cb){
    __shared__ float w1s[Ff*Ff*3];
    __shared__ float cws[Ff];
    for(int i=threadIdx.x;i<Ff*Ff*3;i+=blockDim.x) w1s[i]=w1[i];
    if(threadIdx.x<Ff) cws[threadIdx.x]=cw[threadIdx.x];
    __syncthreads();
    int gid=blockIdx.x*blockDim.x+threadIdx.x;
    int b=gid/Ll, l=gid%Ll;
    float m=mask[b*Ll+l];
    const float* xrow=x+(size_t)(b*Ll+l)*Ff;
    float accu=0.f;
    for(int fo=0;fo<Ff;fo++){
        float a=b1[fo];
        #pragma unroll
        for(int k=0;k<3;k++){
            int ll=l-1+k;
            if(ll>=0&&ll<Ll){
                const float* xp=x+(size_t)(b*Ll+ll)*Ff;
                const float* wp=w1s+fo*(Ff*3)+k;
                #pragma unroll 7
                for(int fi=0;fi<Ff;fi++) a+=xp[fi]*wp[fi*3];
            }
        }
        a*=m;
        a=(a>0.f)?a:(expf(a)-1.f);
        float xfv=a+xrow[fo];
        g_xf[(l*Bb+b)*Ff+fo]=xfv;
        accu+=xfv*cws[fo];
    }
    float ua=accu+cb[0], bm=1e9f*(m-1.f);
    g_ua[l*Bb+b]=ua; g_uab[b*Ll+l]=ua;
    g_bm[l*Bb+b]=bm; g_bmb[b*Ll+l]=bm;
}

__global__ void __launch_bounds__(NTHR,1) scan(
    const float* __restrict__ fc1w, const float* __restrict__ fc1b,
    const float* __restrict__ bih,  const float* __restrict__ bhh,
    const float* __restrict__ w2){

    extern __shared__ __align__(16) char sm[];
    ush*   smB   =(ush*)(sm+OFF_B);
    ush*   smA   =(ush*)(sm+OFF_A);
    float* gates =(float*)(sm+OFF_G);
    float* wa_s  =(float*)(sm+OFF_WAS);
    float* bsum_s=(float*)(sm+OFF_BSUM);
    float* ctxacc=(float*)(sm+OFF_CTXA);
    float* stm   =(float*)(sm+OFF_STM);
    float* stdd  =(float*)(sm+OFF_STM+32);
    const uint32_t saA=smem_u32(sm)+OFF_A;

    const int tid=threadIdx.x, wid=tid>>5, lane=tid&31;
    const int blk=blockIdx.x, mt=blk>>5, nt=blk&31;
    const int mi=wid&3, nig=wid>>2;

    { const char* src=(const char*)&g_wb[(size_t)nt*2*64*BSTRIDE];
      uint32_t dB=smem_u32(sm)+OFF_B;
      for(int i=tid;i<BBYTES/16;i+=NTHR) cpa16(dB+i*16, src+(size_t)i*16);
      CP_COMMIT(); CP_WAIT(0); }
    if(tid<64){ int row=(tid&3)*512 + nt*16 + (tid>>2); bsum_s[tid]=bih[row]+bhh[row]; }
    for(int i=blk*NTHR+tid;i<Bb*32;i+=NBLK*NTHR) g_wapart[i]=0.f;

    const int prow=tid>>2, u0=(tid&3)*4;
    float f1v[4],w2v[4],cst[4];
    #pragma unroll
    for(int j=0;j<4;j++){ f1v[j]=fc1w[nt*16+u0+j]; w2v[j]=w2[nt*16+u0+j]; cst[j]=0.f; }
    const float f1b0=fc1b[0];
    const int chh=nt>>3;
    const size_t hP=(((size_t)(mt*5+chh)*2)*64+prow)*ASTRIDE + (nt&7)*16;
    __syncthreads();
    grid_barrier(blk);

    for(int t=0;t<Ll;t++){
        // ===== Phase A: wa reduce + batch-softmax stats =====
        { float s=0.f; const float4* wp=(const float4*)(g_wapart+tid*32);
          #pragma unroll
          for(int j2=0;j2<8;j2++){ float4 v=__ldcg(wp+j2); s+=v.x+v.y+v.z+v.w; }
          wa_s[tid]=s+f1b0; }
        __syncthreads();
        { int lq=tid>>6, tsub=tid&63, l=blk*4+lq;
          float mx=-1e30f, dd=0.f;
          #pragma unroll
          for(int r2=0;r2<4;r2++){ int b=tsub+r2*64;
            float s=g_ua[l*Bb+b]+wa_s[b]; s=(s>0.f)?s:0.01f*s; s+=g_bm[l*Bb+b];
            float mn=fmaxf(mx,s); dd=dd*__expf(mx-mn)+__expf(s-mn); mx=mn; }
          #pragma unroll
          for(int o=16;o;o>>=1){ float mo=__shfl_down_sync(0xffffffffu,mx,o),d2=__shfl_down_sync(0xffffffffu,dd,o);
            float mn=fmaxf(mx,mo); dd=dd*__expf(mx-mn)+d2*__expf(mo-mn); mx=mn; }
          if((tid&31)==0){ stm[wid]=mx; stdd[wid]=dd; } }
        __syncthreads();
        if(tid<4){
            float m1=stm[tid*2],d1=stdd[tid*2],m2=stm[tid*2+1],d2=stdd[tid*2+1];
            float mn=fmaxf(m1,m2), dd=d1*__expf(m1-mn)+d2*__expf(m2-mn);
            g_stats[(blk*4+tid)*2]=mn; g_stats[(blk*4+tid)*2+1]=1.f/dd;
        }
        grid_barrier(blk);   // G2: stats + wa global

        // ===== Phase B: context + h-GEMM (4 chunks, pipelined) =====
        float C[4][4];
        #pragma unroll
        for(int a=0;a<4;a++){ C[a][0]=0.f;C[a][1]=0.f;C[a][2]=0.f;C[a][3]=0.f; }
        { const char* src=(const char*)&g_ab[(size_t)(mt*5)*2*64*ASTRIDE];
          for(int i=tid;i<ACHB/16;i+=NTHR) cpa16(saA+i*16, src+(size_t)i*16);
          CP_COMMIT(); }
        { int bloc=wid>>2, q4=wid&3, b=blk*2+bloc;
          float wab=wa_s[b], accf=0.f;
          for(int lg=q4*128; lg<q4*128+128; lg+=32){
              int lme=lg+lane;
              float su=g_uab[b*Ll+lme]+wab; su=(su>0.f)?su:0.01f*su; su+=g_bmb[b*Ll+lme];
              float p=__expf(su-__ldcg(&g_stats[lme*2]))*__ldcg(&g_stats[lme*2+1]);
              #pragma unroll
              for(int j2=0;j2<32;j2++){
                  float pj=__shfl_sync(0xffffffffu,p,j2);
                  if(lane<Ff) accf+=pj*g_xf[((lg+j2)*Bb+b)*Ff+lane];
              } }
          if(lane<Ff) ctxacc[(bloc*4+q4)*Ff+lane]=accf; }
        __syncthreads();
        if(tid<2*Ff){
            int bloc=tid/Ff, f=tid-bloc*Ff;
            float s=ctxacc[(bloc*4)*Ff+f]+ctxacc[(bloc*4+1)*Ff+f]+ctxacc[(bloc*4+2)*Ff+f]+ctxacc[(bloc*4+3)*Ff+f];
            int b=blk*2+bloc, mtb=b>>6, rowb=b&63;
            int pos=(f&~15)+pos4(f&15);
            ush hi,lo; bf16split(s,hi,lo);
            size_t base=(((size_t)(mtb*5+4)*2)*64+rowb)*ASTRIDE;
            g_ab[base+pos]=hi;
            g_ab[base+(size_t)64*ASTRIDE+pos]=lo;
        }
        for(int c=0;c<4;c++){
            if(c<3){
                const char* s2=(const char*)&g_ab[(size_t)(mt*5+c+1)*2*64*ASTRIDE];
                uint32_t dA=saA+(uint32_t)((c+1)&1)*ACHB;
                for(int i=tid;i<ACHB/16;i+=NTHR) cpa16(dA+i*16, s2+(size_t)i*16);
                CP_COMMIT(); CP_WAIT(1);
            } else CP_WAIT(0);
            __syncthreads();
            mma_chunk(smA+(c&1)*(ACHB/2), smB, c*128, 8, mi, nig, lane, C);
            __syncthreads();
        }
        mt_barrier(mt);   // ctx visible within mt-group

        // ===== Phase C: ctx chunk (slim 8KB copy) + pointwise =====
        { const char* csrc=(const char*)&g_ab[(size_t)(mt*5+4)*2*64*ASTRIDE];
          for(int i=tid;i<512;i+=NTHR){
              int eoff=((i>>8)*64+((i>>2)&63))*ASTRIDE + (i&3)*8;
              cpa16(saA+(uint32_t)eoff*2, csrc+(size_t)eoff*2);
          }
          CP_COMMIT(); CP_WAIT(0); }
        __syncthreads();
        mma_chunk(smA, smB, 512, 2, mi, nig, lane, C);
        { int r=lane>>2, c4=lane&3;
          #pragma unroll
          for(int ni=0;ni<4;ni++){
              int col=nig*32+ni*8+c4*2;
              *(float2*)&gates[(mi*16+r)*68+col]  =make_float2(C[ni][0],C[ni][1]);
              *(float2*)&gates[(mi*16+r+8)*68+col]=make_float2(C[ni][2],C[ni][3]);
          } }
        __syncthreads();

        ush* hb = g_ab + hP;
        float swa=0.f, sfc=0.f;
        #pragma unroll
        for(int j=0;j<4;j++){
            int u=u0+j;
            float4 g4=*(float4*)&gates[prow*68+u*4];
            float gi=g4.x+bsum_s[u*4+0], gf=g4.y+bsum_s[u*4+1];
            float gg=g4.z+bsum_s[u*4+2], go=g4.w+bsum_s[u*4+3];
            float cn=sigm(gf)*cst[j]+sigm(gi)*tanhf(gg);
            float hn=sigm(go)*tanhf(cn);
            cst[j]=cn;
            swa+=hn*f1v[j]; sfc+=hn*w2v[j];
            ush hi,lo; bf16split(hn,hi,lo);
            int p4=pos4(u);
            hb[p4]=hi; hb[(size_t)64*ASTRIDE+p4]=lo;
        }
        swa+=__shfl_xor_sync(0xffffffffu,swa,1); swa+=__shfl_xor_sync(0xffffffffu,swa,2);
        sfc+=__shfl_xor_sync(0xffffffffu,sfc,1); sfc+=__shfl_xor_sync(0xffffffffu,sfc,2);
        if((tid&3)==0){
            int b=mt*64+prow;
            g_wapart[b*32+nt]=swa;
            g_fcpart[((size_t)t*Bb+b)*32+nt]=sfc;
        }
        grid_barrier(blk);   // G1: h + wapart global
    }
}

__global__ void final_out(const float* __restrict__ x, const float* __restrict__ mask,
                          const float* __restrict__ w2, const float* __restrict__ b2,
                          float* __restrict__ out){
    __shared__ float w2s[Ff];
    if(threadIdx.x<Ff) w2s[threadIdx.x]=w2[512+threadIdx.x];
    __syncthreads();
    int gid=blockIdx.x*blockDim.x+threadIdx.x;
    int b=gid/Ll, l=gid%Ll;
    const float* fp=g_fcpart+(size_t)(l*Bb+b)*32;
    float s=0.f;
    #pragma unroll
    for(int j=0;j<32;j++) s+=fp[j];
    float m=mask[b*Ll+l];
    s*=m;
    const float* xr=x+(size_t)(b*Ll+l)*Ff;
    #pragma unroll 7
    for(int f=0;f<Ff;f++) s+=xr[f]*w2s[f];
    out[b*Ll+l]=(s+b2[0])*m;
}

extern "C" void kernel_launch(void* const* d_in, const int* in_sizes, int n_in,
                              void* d_out, int out_size){
    const float* x=(const float*)d_in[0];
    const float* mask=(const float*)d_in[1];
    const float* conv1w=(const float*)d_in[2];
    const float* conv1b=(const float*)d_in[3];
    const float* convw=(const float*)d_in[4];
    const float* convb=(const float*)d_in[5];
    const float* conv2w=(const float*)d_in[6];
    const float* conv2b=(const float*)d_in[7];
    const float* wih=(const float*)d_in[8];
    const float* whh=(const float*)d_in[9];
    const float* bih=(const float*)d_in[10];
    const float* bhh=(const float*)d_in[11];
    const float* fc1w=(const float*)d_in[12];
    const float* fc1b=(const float*)d_in[13];
    float* out=(float*)d_out;

    cudaFuncSetAttribute(scan, cudaFuncAttributeMaxDynamicSharedMemorySize, SMEM_SZ);
    pack_w<<<(32*64*544+255)/256, 256>>>(whh, wih);
    zero_ab<<<((int)(sizeof(g_ab)/16)+255)/256, 256>>>();
    prep<<<(Bb*Ll)/256, 256>>>(x, mask, conv1w, conv1b, convw, convb);
    scan<<<NBLK, NTHR, SMEM_SZ>>>(fc1w, fc1b, bih, bhh, conv2w);
    final_out<<<(Bb*Ll)/256, 256>>>(x, mask, conv2w, conv2b, out);
}

// round 11
// speedup vs baseline: 1.1157x; 1.1157x over previous
#include <cuda_runtime.h>
#include <cuda_bf16.h>
#include <math.h>
#include <stdint.h>

typedef unsigned short ush;

#define Bb 256
#define Ll 512
#define Ff 28
#define NBLK 128
#define NTHR 256

#define BSTRIDE 552
#define ASTRIDE 136
#define BBYTES  (2*64*BSTRIDE*2)
#define ACHB    (2*64*ASTRIDE*2)   // 34816 bytes per chunk image

#define OFF_B    0
#define OFF_A    141312
#define OFF_G    210944
#define OFF_WAS  228352
#define OFF_BSUM 229376
#define OFF_CTXA 229632
#define SMEM_SZ  230592

__device__ __align__(16) ush g_wb[32*2*64*BSTRIDE];
__device__ __align__(16) ush g_hb[2*4*4*2*64*ASTRIDE];  // [parity][mt][chunk][half][64][136]
__device__ __align__(16) ush g_cb[4*2*64*ASTRIDE];      // [mt][half][64][136]
__device__ float g_xf[Ll*Bb*Ff];
__device__ float g_ua[Ll*Bb];
__device__ float g_bm[Ll*Bb];
__device__ float g_uab[Bb*Ll];
__device__ float g_bmb[Bb*Ll];
__device__ float g_wapart[Bb*32];
__device__ float g_fcpart[(size_t)Ll*Bb*32];
__device__ float g_stats[Ll*2];
__device__ unsigned g_leaf1[8*32];
__device__ unsigned g_root1;
__device__ volatile unsigned g_gen1;
__device__ unsigned g_leaf2[8*32];
__device__ unsigned g_root2;
__device__ volatile unsigned g_gen2;
__device__ unsigned g_mcnt[4*32];
__device__ volatile unsigned g_mgen[4*32];

#define BAR_ATT() asm volatile("bar.sync 1, 128;":::"memory")
#define BAR_GEM() asm volatile("bar.sync 2, 128;":::"memory")

__device__ __forceinline__ void gbar1(int blk){
    __threadfence();
    __syncthreads();
    if(threadIdx.x==0){
        unsigned gen=g_gen1;
        if((atomicAdd(&g_leaf1[(blk&7)*32],1u)&15u)==15u){
            if((atomicAdd(&g_root1,1u)&7u)==7u){ __threadfence(); g_gen1=gen+1; }
        }
        while(g_gen1==gen){}
        __threadfence();
    }
    __syncthreads();
}
// attention-group (warps 4-7) only
__device__ __forceinline__ void gbar2(int blk){
    BAR_ATT();
    if(threadIdx.x==128){
        __threadfence();
        unsigned gen=g_gen2;
        if((atomicAdd(&g_leaf2[(blk&7)*32],1u)&15u)==15u){
            if((atomicAdd(&g_root2,1u)&7u)==7u){ __threadfence(); g_gen2=gen+1; }
        }
        while(g_gen2==gen){}
        __threadfence();
    }
    BAR_ATT();
}
__device__ __forceinline__ void mtbar(int mt){
    BAR_ATT();
    if(threadIdx.x==128){
        __threadfence();
        unsigned gen=g_mgen[mt*32];
        if((atomicAdd(&g_mcnt[mt*32],1u)&31u)==31u){ __threadfence(); g_mgen[mt*32]=gen+1; }
        while(g_mgen[mt*32]==gen){}
        __threadfence();
    }
    BAR_ATT();
}
__device__ __forceinline__ float sigm(float x){ return 1.f/(1.f+__expf(-x)); }
__device__ __forceinline__ int pos4(int km){ return 4*((km&7)>>1)+(km&1)+2*(km>>3); }
__device__ __forceinline__ uint32_t smem_u32(const void* p){
    uint32_t a; asm("{ .reg .u64 t; cvta.to.shared.u64 t, %1; cvt.u32.u64 %0, t; }":"=r"(a):"l"(p)); return a;
}
__device__ __forceinline__ void cpa16(uint32_t s, const void* g){
    asm volatile("cp.async.cg.shared.global [%0], [%1], 16;" :: "r"(s), "l"(g));
}
#define CP_COMMIT() asm volatile("cp.async.commit_group;":::"memory")
#define CP_WAIT(n)  asm volatile("cp.async.wait_group %0;"::"n"(n):"memory")

#define MMA(Cr,A0,A1,A2,A3,B0,B1) \
  asm volatile("mma.sync.aligned.m16n8k16.row.col.f32.bf16.bf16.f32 " \
    "{%0,%1,%2,%3},{%4,%5,%6,%7},{%8,%9},{%0,%1,%2,%3};" \
    : "+f"(Cr[0]),"+f"(Cr[1]),"+f"(Cr[2]),"+f"(Cr[3]) \
    : "r"(A0),"r"(A1),"r"(A2),"r"(A3),"r"(B0),"r"(B1))

__device__ __forceinline__ void bf16split(float v, ush& hi, ush& lo){
    __nv_bfloat16 h=__float2bfloat16(v);
    __nv_bfloat16 l=__float2bfloat16(v-__bfloat162float(h));
    hi=*(ush*)&h; lo=*(ush*)&l;
}

// GEMM-warp version: warp mi covers rows mi*16..+16, ALL 64 N-cols
__device__ __forceinline__ void mma_chunk(const ush* smA, const ush* smB,
        int bK, int ktn, int mi, int lane, float (&C)[8][4]){
    const int r=lane>>2, c4=lane&3;
    const ush* aH = smA + (mi*16+r)*ASTRIDE + c4*4;
    const ush* aL = aH + 64*ASTRIDE;
    const ush* bB = smB + r*BSTRIDE + bK + c4*4;
    for(int kt=0; kt<ktn; kt++){
        int ka=kt*16;
        uint2 a0=*(const uint2*)(aH+ka);
        uint2 a1=*(const uint2*)(aH+8*ASTRIDE+ka);
        uint2 l0=*(const uint2*)(aL+ka);
        uint2 l1=*(const uint2*)(aL+8*ASTRIDE+ka);
        #pragma unroll
        for(int ni=0; ni<8; ni++){
            const ush* bp = bB + ni*8*BSTRIDE + ka;
            uint2 bh=*(const uint2*)bp;
            uint2 bl=*(const uint2*)(bp+64*BSTRIDE);
            MMA(C[ni], a0.x,a1.x,a0.y,a1.y, bh.x,bh.y);
            MMA(C[ni], a0.x,a1.x,a0.y,a1.y, bl.x,bl.y);
            MMA(C[ni], l0.x,l1.x,l0.y,l1.y, bh.x,bh.y);
        }
    }
}

__global__ void pack_w(const float* __restrict__ whh, const float* __restrict__ wih){
    int o=blockIdx.x*blockDim.x+threadIdx.x;
    if(o>=32*64*544) return;
    int nt=o/(64*544); int rem=o-nt*64*544; int j=rem/544; int k=rem%544;
    int row=(j&3)*512 + nt*16 + (j>>2);
    float v = (k<512) ? whh[(size_t)row*512+k] : ((k-512<Ff)? wih[row*Ff+(k-512)] : 0.f);
    ush hi,lo; bf16split(v,hi,lo);
    int pos=(k&~15) + pos4(k&15);
    size_t base=(size_t)nt*2*64*BSTRIDE;
    g_wb[base + (size_t)j*BSTRIDE + pos]=hi;
    g_wb[base + (size_t)64*BSTRIDE + (size_t)j*BSTRIDE + pos]=lo;
}
__global__ void zero_hb(){
    int i=blockIdx.x*blockDim.x+threadIdx.x;
    int nh=(int)(sizeof(g_hb)/16), nc=(int)(sizeof(g_cb)/16);
    if(i<nh) ((uint4*)g_hb)[i]=make_uint4(0,0,0,0);
    else if(i<nh+nc) ((uint4*)g_cb)[i-nh]=make_uint4(0,0,0,0);
}

__global__ void prep(const float* __restrict__ x, const float* __restrict__ mask,
                     const float* __restrict__ w1, const float* __restrict__ b1,
                     const float* __restrict__ cw, const float* __restrict__ cb){
    __shared__ float w1s[Ff*Ff*3];
    __shared__ float cws[Ff];
    for(int i=threadIdx.x;i<Ff*Ff*3;i+=blockDim.x) w1s[i]=w1[i];
    if(threadIdx.x<Ff) cws[threadIdx.x]=cw[threadIdx.x];
    __syncthreads();
    int gid=blockIdx.x*blockDim.x+threadIdx.x;
    int b=gid/Ll, l=gid%Ll;
    float m=mask[b*Ll+l];
    const float* xrow=x+(size_t)(b*Ll+l)*Ff;
    float accu=0.f;
    for(int fo=0;fo<Ff;fo++){
        float a=b1[fo];
        #pragma unroll
        for(int k=0;k<3;k++){
            int ll=l-1+k;
            if(ll>=0&&ll<Ll){
                const float* xp=x+(size_t)(b*Ll+ll)*Ff;
                const float* wp=w1s+fo*(Ff*3)+k;
                #pragma unroll 7
                for(int fi=0;fi<Ff;fi++) a+=xp[fi]*wp[fi*3];
            }
        }
        a*=m;
        a=(a>0.f)?a:(expf(a)-1.f);
        float xfv=a+xrow[fo];
        g_xf[(l*Bb+b)*Ff+fo]=xfv;
        accu+=xfv*cws[fo];
    }
    float ua=accu+cb[0], bm=1e9f*(m-1.f);
    g_ua[l*Bb+b]=ua; g_uab[b*Ll+l]=ua;
    g_bm[l*Bb+b]=bm; g_bmb[b*Ll+l]=bm;
}

__global__ void __launch_bounds__(NTHR,1) scan(
    const float* __restrict__ fc1w, const float* __restrict__ fc1b,
    const float* __restrict__ bih,  const float* __restrict__ bhh,
    const float* __restrict__ w2){

    extern __shared__ __align__(16) char sm[];
    ush*   smB   =(ush*)(sm+OFF_B);
    ush*   smA   =(ush*)(sm+OFF_A);
    float* gates =(float*)(sm+OFF_G);
    float* wa_s  =(float*)(sm+OFF_WAS);
    float* bsum_s=(float*)(sm+OFF_BSUM);
    float* ctxacc=(float*)(sm+OFF_CTXA);
    const uint32_t saA=smem_u32(sm)+OFF_A;

    const int tid=threadIdx.x, wid=tid>>5, lane=tid&31;
    const int blk=blockIdx.x, mt=blk>>5, nt=blk&31;
    const int gw=(wid<4);     // gemm group
    const int mi=wid&3;

    { const char* src=(const char*)&g_wb[(size_t)nt*2*64*BSTRIDE];
      uint32_t dB=smem_u32(sm)+OFF_B;
      for(int i=tid;i<BBYTES/16;i+=NTHR) cpa16(dB+i*16, src+(size_t)i*16);
      CP_COMMIT(); CP_WAIT(0); }
    if(tid<64){ int row=(tid&3)*512 + nt*16 + (tid>>2); bsum_s[tid]=bih[row]+bhh[row]; }
    for(int i=blk*NTHR+tid;i<Bb*32;i+=NBLK*NTHR) g_wapart[i]=0.f;

    const int prow=tid>>2, u0=(tid&3)*4;
    float f1v[4],w2v[4],cst[4];
    #pragma unroll
    for(int j=0;j<4;j++){ f1v[j]=fc1w[nt*16+u0+j]; w2v[j]=w2[nt*16+u0+j]; cst[j]=0.f; }
    const float f1b0=fc1b[0];
    const int chh=nt>>3;
    const size_t hP0=((((size_t)0*4+mt)*4+chh)*2*64 + prow)*ASTRIDE + (nt&7)*16;
    const size_t hP1=((((size_t)1*4+mt)*4+chh)*2*64 + prow)*ASTRIDE + (nt&7)*16;
    __syncthreads();
    gbar1(blk);

    float C[8][4];
    for(int t=0;t<Ll;t++){
        const int rp=(t&1)^1;   // read parity (h(t-1))
        if(gw){
            // ===== GEMM lane: stream h chunks, MMA (no dep on stats/ctx) =====
            #pragma unroll
            for(int a=0;a<8;a++){ C[a][0]=0.f;C[a][1]=0.f;C[a][2]=0.f;C[a][3]=0.f; }
            const char* base=(const char*)&g_hb[(((size_t)rp*4+mt)*4)*2*64*ASTRIDE];
            for(int i=tid;i<ACHB/16;i+=128) cpa16(saA+i*16, base+(size_t)i*16);
            CP_COMMIT();
            for(int i=tid;i<ACHB/16;i+=128) cpa16(saA+ACHB+i*16, base+(size_t)ACHB+(size_t)i*16);
            CP_COMMIT();
            for(int c=0;c<4;c++){
                if(c<3) CP_WAIT(1); else CP_WAIT(0);
                BAR_GEM();
                mma_chunk(smA+(c&1)*(ACHB/2), smB, c*128, 8, mi, lane, C);
                BAR_GEM();
                if(c<2){
                    const char* s2=base+(size_t)(c+2)*ACHB;
                    uint32_t dA=saA+(uint32_t)(c&1)*ACHB;
                    for(int i=tid;i<ACHB/16;i+=128) cpa16(dA+i*16, s2+(size_t)i*16);
                    CP_COMMIT();
                }
            }
        } else {
            // ===== Attention lane =====
            const int tid2=tid-128, aw=wid-4;
            #pragma unroll
            for(int rep=0;rep<2;rep++){
                int b=tid2+rep*128;
                float s=0.f; const float4* wp=(const float4*)(g_wapart+b*32);
                #pragma unroll
                for(int j2=0;j2<8;j2++){ float4 v=__ldcg(wp+j2); s+=v.x+v.y+v.z+v.w; }
                wa_s[b]=s+f1b0;
            }
            BAR_ATT();
            { int l=blk*4+aw;
              float mx=-1e30f, dd=0.f;
              #pragma unroll
              for(int r2=0;r2<8;r2++){ int b=lane+r2*32;
                float s=g_ua[l*Bb+b]+wa_s[b]; s=(s>0.f)?s:0.01f*s; s+=g_bm[l*Bb+b];
                float mn=fmaxf(mx,s); dd=dd*__expf(mx-mn)+__expf(s-mn); mx=mn; }
              #pragma unroll
              for(int o=16;o;o>>=1){ float mo=__shfl_down_sync(0xffffffffu,mx,o),d2=__shfl_down_sync(0xffffffffu,dd,o);
                float mn=fmaxf(mx,mo); dd=dd*__expf(mx-mn)+d2*__expf(mo-mn); mx=mn; }
              if(lane==0){ g_stats[l*2]=mx; g_stats[l*2+1]=1.f/dd; } }
            gbar2(blk);
            { int bloc=aw>>1, half=aw&1, b=blk*2+bloc;
              float wab=wa_s[b], accf=0.f;
              for(int lg=half*256; lg<half*256+256; lg+=32){
                  int lme=lg+lane;
                  float su=g_uab[b*Ll+lme]+wab; su=(su>0.f)?su:0.01f*su; su+=g_bmb[b*Ll+lme];
                  float p=__expf(su-__ldcg(&g_stats[lme*2]))*__ldcg(&g_stats[lme*2+1]);
                  #pragma unroll
                  for(int j2=0;j2<32;j2++){
                      float pj=__shfl_sync(0xffffffffu,p,j2);
                      if(lane<Ff) accf+=pj*g_xf[((lg+j2)*Bb+b)*Ff+lane];
                  } }
              if(lane<Ff) ctxacc[(bloc*2+half)*Ff+lane]=accf; }
            BAR_ATT();
            if(tid2<2*Ff){
                int bloc=tid2/Ff, f=tid2-bloc*Ff;
                float s=ctxacc[(bloc*2)*Ff+f]+ctxacc[(bloc*2+1)*Ff+f];
                int b=blk*2+bloc, mtb=b>>6, rowb=b&63;
                int pos=(f&~15)+pos4(f&15);
                ush hi,lo; bf16split(s,hi,lo);
                size_t bmt=(size_t)mtb*2*64*ASTRIDE;
                g_cb[bmt + (size_t)rowb*ASTRIDE + pos]=hi;
                g_cb[bmt + (size_t)(64+rowb)*ASTRIDE + pos]=lo;
            }
            mtbar(mt);
        }
        __syncthreads();   // join lanes

        // slim 8KB ctx copy into buffer 0 (all threads)
        { const char* csrc=(const char*)&g_cb[(size_t)mt*2*64*ASTRIDE];
          for(int i=tid;i<512;i+=NTHR){
              int eoff=((i>>8)*64+((i>>2)&63))*ASTRIDE + (i&3)*8;
              cpa16(saA+(uint32_t)eoff*2, csrc+(size_t)eoff*2);
          }
          CP_COMMIT(); CP_WAIT(0); }
        __syncthreads();
        if(gw){
            mma_chunk(smA, smB, 512, 2, mi, lane, C);
            int r=lane>>2, c4=lane&3;
            #pragma unroll
            for(int ni=0;ni<8;ni++){
                int col=ni*8+c4*2;
                *(float2*)&gates[(mi*16+r)*68+col]  =make_float2(C[ni][0],C[ni][1]);
                *(float2*)&gates[(mi*16+r+8)*68+col]=make_float2(C[ni][2],C[ni][3]);
            }
        }
        __syncthreads();

        // ===== pointwise (all warps) =====
        ush* hb = g_hb + ((t&1)? hP1 : hP0);
        float swa=0.f, sfc=0.f;
        #pragma unroll
        for(int j=0;j<4;j++){
            int u=u0+j;
            float4 g4=*(float4*)&gates[prow*68+u*4];
            float gi=g4.x+bsum_s[u*4+0], gf=g4.y+bsum_s[u*4+1];
            float gg=g4.z+bsum_s[u*4+2], go=g4.w+bsum_s[u*4+3];
            float cn=sigm(gf)*cst[j]+sigm(gi)*tanhf(gg);
            float hn=sigm(go)*tanhf(cn);
            cst[j]=cn;
            swa+=hn*f1v[j]; sfc+=hn*w2v[j];
            ush hi,lo; bf16split(hn,hi,lo);
            int p4=pos4(u);
            hb[p4]=hi; hb[(size_t)64*ASTRIDE+p4]=lo;
        }
        swa+=__shfl_xor_sync(0xffffffffu,swa,1); swa+=__shfl_xor_sync(0xffffffffu,swa,2);
        sfc+=__shfl_xor_sync(0xffffffffu,sfc,1); sfc+=__shfl_xor_sync(0xffffffffu,sfc,2);
        if((tid&3)==0){
            int b=mt*64+prow;
            g_wapart[b*32+nt]=swa;
            g_fcpart[((size_t)t*Bb+b)*32+nt]=sfc;
        }
        gbar1(blk);   // h + wapart global
    }
}

__global__ void final_out(const float* __restrict__ x, const float* __restrict__ mask,
                          const float* __restrict__ w2, const float* __restrict__ b2,
                          float* __restrict__ out){
    __shared__ float w2s[Ff];
    if(threadIdx.x<Ff) w2s[threadIdx.x]=w2[512+threadIdx.x];
    __syncthreads();
    int gid=blockIdx.x*blockDim.x+threadIdx.x;
    int b=gid/Ll, l=gid%Ll;
    const float* fp=g_fcpart+(size_t)(l*Bb+b)*32;
    float s=0.f;
    #pragma unroll
    for(int j=0;j<32;j++) s+=fp[j];
    float m=mask[b*Ll+l];
    s*=m;
    const float* xr=x+(size_t)(b*Ll+l)*Ff;
    #pragma unroll 7
    for(int f=0;f<Ff;f++) s+=xr[f]*w2s[f];
    out[b*Ll+l]=(s+b2[0])*m;
}

extern "C" void kernel_launch(void* const* d_in, const int* in_sizes, int n_in,
                              void* d_out, int out_size){
    const float* x=(const float*)d_in[0];
    const float* mask=(const float*)d_in[1];
    const float* conv1w=(const float*)d_in[2];
    const float* conv1b=(const float*)d_in[3];
    const float* convw=(const float*)d_in[4];
    const float* convb=(const float*)d_in[5];
    const float* conv2w=(const float*)d_in[6];
    const float* conv2b=(const float*)d_in[7];
    const float* wih=(const float*)d_in[8];
    const float* whh=(const float*)d_in[9];
    const float* bih=(const float*)d_in[10];
    const float* bhh=(const float*)d_in[11];
    const float* fc1w=(const float*)d_in[12];
    const float* fc1b=(const float*)d_in[13];
    float* out=(float*)d_out;

    cudaFuncSetAttribute(scan, cudaFuncAttributeMaxDynamicSharedMemorySize, SMEM_SZ);
    pack_w<<<(32*64*544+255)/256, 256>>>(whh, wih);
    zero_hb<<<((int)((sizeof(g_hb)+sizeof(g_cb))/16)+255)/256, 256>>>();
    prep<<<(Bb*Ll)/256, 256>>>(x, mask, conv1w, conv1b, convw, convb);
    scan<<<NBLK, NTHR, SMEM_SZ>>>(fc1w, fc1b, bih, bhh, conv2w);
    final_out<<<(Bb*Ll)/256, 256>>>(x, mask, conv2w, conv2b, out);
}

// round 12
// speedup vs baseline: 1.2718x; 1.1399x over previous
#include <cuda_runtime.h>
#include <cuda_bf16.h>
#include <math.h>
#include <stdint.h>

typedef unsigned short ush;

#define Bb 256
#define Ll 512
#define Ff 28
#define NBLK 128
#define NTHR 256

#define BSTRIDE 552
#define ASTRIDE 136
#define BBYTES  (2*64*BSTRIDE*2)
#define ACHB    (2*64*ASTRIDE*2)   // 34816

#define OFF_B     0
#define OFF_A     141312
#define OFF_GATES (OFF_A+ACHB)
#define OFF_WAS   210944
#define OFF_BSUM  211200
#define OFF_CTXA  211456
#define OFF_SUA   211968
#define OFF_SBM   216064
#define OFF_SUAB  220160
#define OFF_SBMB  224256
#define SMEM_SZ   228352

__device__ __align__(16) ush g_wb[32*2*64*BSTRIDE];
__device__ __align__(16) ush g_hb[2*4*4*2*64*ASTRIDE];  // [parity][mt][chunk][half][64][136]
__device__ __align__(16) ush g_cb[4*2*64*ASTRIDE];      // [mt][half][64][136]
__device__ float g_xf[Ll*Bb*Ff];
__device__ float g_ua[Ll*Bb];
__device__ float g_bm[Ll*Bb];
__device__ float g_uab[Bb*Ll];
__device__ float g_bmb[Bb*Ll];
__device__ float g_wapart[Bb*32];
__device__ float g_fcpart[(size_t)Ll*Bb*32];
__device__ __align__(16) float g_pstat[2*512*4*2];      // [parity][l][mt]{m,d}
__device__ unsigned g_leaf1[8*32];
__device__ unsigned g_root1;
__device__ volatile unsigned g_gen1;
__device__ unsigned g_mc1[4*32];
__device__ volatile unsigned g_mg1[4*32];
__device__ unsigned g_mc2[4*32];
__device__ volatile unsigned g_mg2[4*32];

#define BAR_ATT() asm volatile("bar.sync 1, 128;":::"memory")
#define BAR_GEM() asm volatile("bar.sync 2, 128;":::"memory")

__device__ __forceinline__ void gbar_arrive_wait(int blk){
    unsigned gen=g_gen1;
    __threadfence();
    if((atomicAdd(&g_leaf1[(blk&7)*32],1u)&15u)==15u){
        if((atomicAdd(&g_root1,1u)&7u)==7u){ __threadfence(); g_gen1=gen+1; }
    }
    while(g_gen1==gen){}
    __threadfence();
}
__device__ __forceinline__ void gbar_full(int blk){
    __threadfence();
    __syncthreads();
    if(threadIdx.x==0) gbar_arrive_wait(blk);
    __syncthreads();
}
// global stats barrier: attention lane only (warps 4-7)
__device__ __forceinline__ void gbarG(int blk){
    BAR_ATT();
    if(threadIdx.x==128) gbar_arrive_wait(blk);
    BAR_ATT();
}
// ctx barrier: attention lane only, mt-scope
__device__ __forceinline__ void mtbar_ctx(int mt){
    BAR_ATT();
    if(threadIdx.x==128){
        __threadfence();
        unsigned gen=g_mg1[mt*32];
        if((atomicAdd(&g_mc1[mt*32],1u)&31u)==31u){ __threadfence(); g_mg1[mt*32]=gen+1; }
        while(g_mg1[mt*32]==gen){}
        __threadfence();
    }
    BAR_ATT();
}
// end-of-step barrier: block-wide, mt-scope
__device__ __forceinline__ void mtbar_end(int mt){
    __threadfence();
    __syncthreads();
    if(threadIdx.x==0){
        unsigned gen=g_mg2[mt*32];
        if((atomicAdd(&g_mc2[mt*32],1u)&31u)==31u){ __threadfence(); g_mg2[mt*32]=gen+1; }
        while(g_mg2[mt*32]==gen){}
        __threadfence();
    }
    __syncthreads();
}
__device__ __forceinline__ float sigm(float x){ return 1.f/(1.f+__expf(-x)); }
__device__ __forceinline__ int pos4(int km){ return 4*((km&7)>>1)+(km&1)+2*(km>>3); }
__device__ __forceinline__ uint32_t smem_u32(const void* p){
    uint32_t a; asm("{ .reg .u64 t; cvta.to.shared.u64 t, %1; cvt.u32.u64 %0, t; }":"=r"(a):"l"(p)); return a;
}
__device__ __forceinline__ void cpa16(uint32_t s, const void* g){
    asm volatile("cp.async.cg.shared.global [%0], [%1], 16;" :: "r"(s), "l"(g));
}
#define CP_COMMIT() asm volatile("cp.async.commit_group;":::"memory")
#define CP_WAIT(n)  asm volatile("cp.async.wait_group %0;"::"n"(n):"memory")

#define MMA(Cr,A0,A1,A2,A3,B0,B1) \
  asm volatile("mma.sync.aligned.m16n8k16.row.col.f32.bf16.bf16.f32 " \
    "{%0,%1,%2,%3},{%4,%5,%6,%7},{%8,%9},{%0,%1,%2,%3};" \
    : "+f"(Cr[0]),"+f"(Cr[1]),"+f"(Cr[2]),"+f"(Cr[3]) \
    : "r"(A0),"r"(A1),"r"(A2),"r"(A3),"r"(B0),"r"(B1))

__device__ __forceinline__ void bf16split(float v, ush& hi, ush& lo){
    __nv_bfloat16 h=__float2bfloat16(v);
    __nv_bfloat16 l=__float2bfloat16(v-__bfloat162float(h));
    hi=*(ush*)&h; lo=*(ush*)&l;
}

// GEMM-warp: warp mi covers rows mi*16..+16, all 64 N-cols
__device__ __forceinline__ void mma_chunk(const ush* smA, const ush* smB,
        int bK, int ktn, int mi, int lane, float (&C)[8][4]){
    const int r=lane>>2, c4=lane&3;
    const ush* aH = smA + (mi*16+r)*ASTRIDE + c4*4;
    const ush* aL = aH + 64*ASTRIDE;
    const ush* bB = smB + r*BSTRIDE + bK + c4*4;
    for(int kt=0; kt<ktn; kt++){
        int ka=kt*16;
        uint2 a0=*(const uint2*)(aH+ka);
        uint2 a1=*(const uint2*)(aH+8*ASTRIDE+ka);
        uint2 l0=*(const uint2*)(aL+ka);
        uint2 l1=*(const uint2*)(aL+8*ASTRIDE+ka);
        #pragma unroll
        for(int ni=0; ni<8; ni++){
            const ush* bp = bB + ni*8*BSTRIDE + ka;
            uint2 bh=*(const uint2*)bp;
            uint2 bl=*(const uint2*)(bp+64*BSTRIDE);
            MMA(C[ni], a0.x,a1.x,a0.y,a1.y, bh.x,bh.y);
            MMA(C[ni], a0.x,a1.x,a0.y,a1.y, bl.x,bl.y);
            MMA(C[ni], l0.x,l1.x,l0.y,l1.y, bh.x,bh.y);
        }
    }
}

__global__ void pack_w(const float* __restrict__ whh, const float* __restrict__ wih){
    int o=blockIdx.x*blockDim.x+threadIdx.x;
    if(o>=32*64*544) return;
    int nt=o/(64*544); int rem=o-nt*64*544; int j=rem/544; int k=rem%544;
    int row=(j&3)*512 + nt*16 + (j>>2);
    float v = (k<512) ? whh[(size_t)row*512+k] : ((k-512<Ff)? wih[row*Ff+(k-512)] : 0.f);
    ush hi,lo; bf16split(v,hi,lo);
    int pos=(k&~15) + pos4(k&15);
    size_t base=(size_t)nt*2*64*BSTRIDE;
    g_wb[base + (size_t)j*BSTRIDE + pos]=hi;
    g_wb[base + (size_t)64*BSTRIDE + (size_t)j*BSTRIDE + pos]=lo;
}
__global__ void zero_hb(){
    int i=blockIdx.x*blockDim.x+threadIdx.x;
    int nh=(int)(sizeof(g_hb)/16), nc=(int)(sizeof(g_cb)/16);
    if(i<nh) ((uint4*)g_hb)[i]=make_uint4(0,0,0,0);
    else if(i<nh+nc) ((uint4*)g_cb)[i-nh]=make_uint4(0,0,0,0);
}

__global__ void prep(const float* __restrict__ x, const float* __restrict__ mask,
                     const float* __restrict__ w1, const float* __restrict__ b1,
                     const float* __restrict__ cw, const float* __restrict__ cb){
    __shared__ float w1s[Ff*Ff*3];
    __shared__ float cws[Ff];
    for(int i=threadIdx.x;i<Ff*Ff*3;i+=blockDim.x) w1s[i]=w1[i];
    if(threadIdx.x<Ff) cws[threadIdx.x]=cw[threadIdx.x];
    __syncthreads();
    int gid=blockIdx.x*blockDim.x+threadIdx.x;
    int b=gid/Ll, l=gid%Ll;
    float m=mask[b*Ll+l];
    const float* xrow=x+(size_t)(b*Ll+l)*Ff;
    float accu=0.f;
    for(int fo=0;fo<Ff;fo++){
        float a=b1[fo];
        #pragma unroll
        for(int k=0;k<3;k++){
            int ll=l-1+k;
            if(ll>=0&&ll<Ll){
                const float* xp=x+(size_t)(b*Ll+ll)*Ff;
                const float* wp=w1s+fo*(Ff*3)+k;
                #pragma unroll 7
                for(int fi=0;fi<Ff;fi++) a+=xp[fi]*wp[fi*3];
            }
        }
        a*=m;
        a=(a>0.f)?a:(expf(a)-1.f);
        float xfv=a+xrow[fo];
        g_xf[(l*Bb+b)*Ff+fo]=xfv;
        accu+=xfv*cws[fo];
    }
    float ua=accu+cb[0], bm=1e9f*(m-1.f);
    g_ua[l*Bb+b]=ua; g_uab[b*Ll+l]=ua;
    g_bm[l*Bb+b]=bm; g_bmb[b*Ll+l]=bm;
}

__global__ void __launch_bounds__(NTHR,1) scan(
    const float* __restrict__ fc1w, const float* __restrict__ fc1b,
    const float* __restrict__ bih,  const float* __restrict__ bhh,
    const float* __restrict__ w2){

    extern __shared__ __align__(16) char sm[];
    ush*   smB   =(ush*)(sm+OFF_B);
    ush*   smA   =(ush*)(sm+OFF_A);
    float* gates =(float*)(sm+OFF_GATES);
    float* wa_s  =(float*)(sm+OFF_WAS);
    float* bsum_s=(float*)(sm+OFF_BSUM);
    float* ctxacc=(float*)(sm+OFF_CTXA);
    float* sua   =(float*)(sm+OFF_SUA);
    float* sbm   =(float*)(sm+OFF_SBM);
    float* suab  =(float*)(sm+OFF_SUAB);
    float* sbmb  =(float*)(sm+OFF_SBMB);
    const uint32_t saA=smem_u32(sm)+OFF_A;

    const int tid=threadIdx.x, wid=tid>>5, lane=tid&31;
    const int blk=blockIdx.x, mt=blk>>5, nt=blk&31;
    const int gw=(wid<4);
    const int mi=wid&3;

    { const char* src=(const char*)&g_wb[(size_t)nt*2*64*BSTRIDE];
      uint32_t dB=smem_u32(sm)+OFF_B;
      for(int i=tid;i<BBYTES/16;i+=NTHR) cpa16(dB+i*16, src+(size_t)i*16);
      CP_COMMIT(); CP_WAIT(0); }
    if(tid<64){ int row=(tid&3)*512 + nt*16 + (tid>>2); bsum_s[tid]=bih[row]+bhh[row]; }
    // static caches
    for(int i=tid;i<16*64;i+=NTHR){
        int lo2=i>>6, b=i&63;
        sua[i]=g_ua[(nt*16+lo2)*Bb + mt*64+b];
        sbm[i]=g_bm[(nt*16+lo2)*Bb + mt*64+b];
    }
    for(int i=tid;i<2*Ll;i+=NTHR){
        int bl=i>>9, l=i&511;
        suab[i]=g_uab[(mt*64+nt*2+bl)*Ll + l];
        sbmb[i]=g_bmb[(mt*64+nt*2+bl)*Ll + l];
    }
    for(int i=blk*NTHR+tid;i<Bb*32;i+=NBLK*NTHR) g_wapart[i]=0.f;

    const int prow=tid>>2, u0=(tid&3)*4;
    float f1v[4],w2v[4],cst[4];
    #pragma unroll
    for(int j=0;j<4;j++){ f1v[j]=fc1w[nt*16+u0+j]; w2v[j]=w2[nt*16+u0+j]; cst[j]=0.f; }
    const float f1b0=fc1b[0];
    const int chh=nt>>3;
    const size_t hP0=((((size_t)0*4+mt)*4+chh)*2*64 + prow)*ASTRIDE + (nt&7)*16;
    const size_t hP1=((((size_t)1*4+mt)*4+chh)*2*64 + prow)*ASTRIDE + (nt&7)*16;
    __syncthreads();
    gbar_full(blk);

    float C[8][4];
    for(int t=0;t<Ll;t++){
        const int rp=(t&1)^1;
        const int par=t&1;
        if(gw){
            // ===== GEMM lane: stream h chunks (parity rp) + MMA =====
            #pragma unroll
            for(int a=0;a<8;a++){ C[a][0]=0.f;C[a][1]=0.f;C[a][2]=0.f;C[a][3]=0.f; }
            const char* base=(const char*)&g_hb[(((size_t)rp*4+mt)*4)*2*64*ASTRIDE];
            for(int i=tid;i<ACHB/16;i+=128) cpa16(saA+i*16, base+(size_t)i*16);
            CP_COMMIT();
            for(int i=tid;i<ACHB/16;i+=128) cpa16(saA+ACHB+i*16, base+(size_t)ACHB+(size_t)i*16);
            CP_COMMIT();
            for(int c=0;c<4;c++){
                if(c<3) CP_WAIT(1); else CP_WAIT(0);
                BAR_GEM();
                mma_chunk(smA+(c&1)*(ACHB/2), smB, c*128, 8, mi, lane, C);
                BAR_GEM();
                if(c<2){
                    const char* s2=base+(size_t)(c+2)*ACHB;
                    uint32_t dA=saA+(uint32_t)(c&1)*ACHB;
                    for(int i=tid;i<ACHB/16;i+=128) cpa16(dA+i*16, s2+(size_t)i*16);
                    CP_COMMIT();
                }
            }
        } else {
            // ===== Attention lane =====
            const int tid2=tid-128, aw=wid-4;
            // wa reduce over own mt's 64 batches (2 threads per batch)
            { int bl=tid2>>1, q=tid2&1;
              const float4* wp=(const float4*)(g_wapart+(mt*64+bl)*32+q*16);
              float s=0.f;
              #pragma unroll
              for(int j2=0;j2<4;j2++){ float4 v=__ldcg(wp+j2); s+=v.x+v.y+v.z+v.w; }
              s+=__shfl_xor_sync(0xffffffffu,s,1);
              if(q==0) wa_s[bl]=s+f1b0;
            }
            BAR_ATT();
            // partial stats: 16 l x 64 b (own mt batches), 4 l per warp, 8 lanes per l
            { int lsub=lane>>3, lloc=aw*4+lsub, bg=(lane&7)*8;
              float mx=-1e30f, dd=0.f;
              #pragma unroll
              for(int j2=0;j2<8;j2++){
                  int b=bg+j2;
                  float s=sua[lloc*64+b]+wa_s[b];
                  s=(s>0.f)?s:0.01f*s; s+=sbm[lloc*64+b];
                  float mn=fmaxf(mx,s); dd=dd*__expf(mx-mn)+__expf(s-mn); mx=mn;
              }
              #pragma unroll
              for(int o=1;o<8;o<<=1){
                  float mo=__shfl_xor_sync(0xffffffffu,mx,o);
                  float d2=__shfl_xor_sync(0xffffffffu,dd,o);
                  float mn=fmaxf(mx,mo); dd=dd*__expf(mx-mn)+d2*__expf(mo-mn); mx=mn;
              }
              if((lane&7)==0){
                  float2* dst=(float2*)&g_pstat[((par*512)+(nt*16+lloc))*8 + mt*2];
                  float2 v; v.x=mx; v.y=dd;
                  __stcg(dst, v);
              }
            }
            gbarG(blk);   // the ONE global barrier: stats partials
            // context: warp aw -> batch nt*2+(aw>>1), half (aw&1)
            { int bloc=aw>>1, half=aw&1;
              int bL=nt*2+bloc, b=mt*64+bL;
              float wab=wa_s[bL], accf=0.f;
              for(int lg=half*256; lg<half*256+256; lg+=32){
                  int lme=lg+lane;
                  float su=suab[bloc*512+lme]+wab;
                  su=(su>0.f)?su:0.01f*su; su+=sbmb[bloc*512+lme];
                  const float4* ps=(const float4*)&g_pstat[(par*512+lme)*8];
                  float4 p0=__ldcg(ps), p1=__ldcg(ps+1);
                  float M=fmaxf(fmaxf(p0.x,p0.z),fmaxf(p1.x,p1.z));
                  float D=p0.y*__expf(p0.x-M)+p0.w*__expf(p0.z-M)
                         +p1.y*__expf(p1.x-M)+p1.w*__expf(p1.z-M);
                  float p=__expf(su-M)*__frcp_rn(D);
                  #pragma unroll
                  for(int j2=0;j2<32;j2++){
                      float pj=__shfl_sync(0xffffffffu,p,j2);
                      if(lane<Ff) accf+=pj*g_xf[((lg+j2)*Bb+b)*Ff+lane];
                  }
              }
              if(lane<Ff) ctxacc[(bloc*2+half)*Ff+lane]=accf;
            }
            BAR_ATT();
            if(tid2<2*Ff){
                int bloc=tid2/Ff, f=tid2-bloc*Ff;
                float s=ctxacc[(bloc*2)*Ff+f]+ctxacc[(bloc*2+1)*Ff+f];
                int rowb=nt*2+bloc;
                int pos=(f&~15)+pos4(f&15);
                ush hi,lo; bf16split(s,hi,lo);
                size_t bmt=(size_t)mt*2*64*ASTRIDE;
                g_cb[bmt + (size_t)rowb*ASTRIDE + pos]=hi;
                g_cb[bmt + (size_t)(64+rowb)*ASTRIDE + pos]=lo;
            }
            mtbar_ctx(mt);
        }
        __syncthreads();   // join lanes

        // slim 8KB ctx copy into A buffer 0 (all threads)
        { const char* csrc=(const char*)&g_cb[(size_t)mt*2*64*ASTRIDE];
          for(int i=tid;i<512;i+=NTHR){
              int eoff=((i>>8)*64+((i>>2)&63))*ASTRIDE + (i&3)*8;
              cpa16(saA+(uint32_t)eoff*2, csrc+(size_t)eoff*2);
          }
          CP_COMMIT(); CP_WAIT(0); }
        __syncthreads();
        if(gw){
            mma_chunk(smA, smB, 512, 2, mi, lane, C);
            int r=lane>>2, c4=lane&3;
            #pragma unroll
            for(int ni=0;ni<8;ni++){
                int col=ni*8+c4*2;
                *(float2*)&gates[(mi*16+r)*68+col]  =make_float2(C[ni][0],C[ni][1]);
                *(float2*)&gates[(mi*16+r+8)*68+col]=make_float2(C[ni][2],C[ni][3]);
            }
        }
        __syncthreads();

        // ===== pointwise (all warps) =====
        ush* hb = g_hb + ((t&1)? hP1 : hP0);
        float swa=0.f, sfc=0.f;
        #pragma unroll
        for(int j=0;j<4;j++){
            int u=u0+j;
            float4 g4=*(float4*)&gates[prow*68+u*4];
            float gi=g4.x+bsum_s[u*4+0], gf=g4.y+bsum_s[u*4+1];
            float gg=g4.z+bsum_s[u*4+2], go=g4.w+bsum_s[u*4+3];
            float cn=sigm(gf)*cst[j]+sigm(gi)*tanhf(gg);
            float hn=sigm(go)*tanhf(cn);
            cst[j]=cn;
            swa+=hn*f1v[j]; sfc+=hn*w2v[j];
            ush hi,lo; bf16split(hn,hi,lo);
            int p4=pos4(u);
            hb[p4]=hi; hb[(size_t)64*ASTRIDE+p4]=lo;
        }
        swa+=__shfl_xor_sync(0xffffffffu,swa,1); swa+=__shfl_xor_sync(0xffffffffu,swa,2);
        sfc+=__shfl_xor_sync(0xffffffffu,sfc,1); sfc+=__shfl_xor_sync(0xffffffffu,sfc,2);
        if((tid&3)==0){
            int b=mt*64+prow;
            g_wapart[b*32+nt]=swa;
            g_fcpart[((size_t)t*Bb+b)*32+nt]=sfc;
        }
        mtbar_end(mt);   // h + wapart + ctx-consumed, mt-scope
    }
}

__global__ void final_out(const float* __restrict__ x, const float* __restrict__ mask,
                          const float* __restrict__ w2, const float* __restrict__ b2,
                          float* __restrict__ out){
    __shared__ float w2s[Ff];
    if(threadIdx.x<Ff) w2s[threadIdx.x]=w2[512+threadIdx.x];
    __syncthreads();
    int gid=blockIdx.x*blockDim.x+threadIdx.x;
    int b=gid/Ll, l=gid%Ll;
    const float* fp=g_fcpart+(size_t)(l*Bb+b)*32;
    float s=0.f;
    #pragma unroll
    for(int j=0;j<32;j++) s+=fp[j];
    float m=mask[b*Ll+l];
    s*=m;
    const float* xr=x+(size_t)(b*Ll+l)*Ff;
    #pragma unroll 7
    for(int f=0;f<Ff;f++) s+=xr[f]*w2s[f];
    out[b*Ll+l]=(s+b2[0])*m;
}

extern "C" void kernel_launch(void* const* d_in, const int* in_sizes, int n_in,
                              void* d_out, int out_size){
    const float* x=(const float*)d_in[0];
    const float* mask=(const float*)d_in[1];
    const float* conv1w=(const float*)d_in[2];
    const float* conv1b=(const float*)d_in[3];
    const float* convw=(const float*)d_in[4];
    const float* convb=(const float*)d_in[5];
    const float* conv2w=(const float*)d_in[6];
    const float* conv2b=(const float*)d_in[7];
    const float* wih=(const float*)d_in[8];
    const float* whh=(const float*)d_in[9];
    const float* bih=(const float*)d_in[10];
    const float* bhh=(const float*)d_in[11];
    const float* fc1w=(const float*)d_in[12];
    const float* fc1b=(const float*)d_in[13];
    float* out=(float*)d_out;

    cudaFuncSetAttribute(scan, cudaFuncAttributeMaxDynamicSharedMemorySize, SMEM_SZ);
    pack_w<<<(32*64*544+255)/256, 256>>>(whh, wih);
    zero_hb<<<((int)((sizeof(g_hb)+sizeof(g_cb))/16)+255)/256, 256>>>();
    prep<<<(Bb*Ll)/256, 256>>>(x, mask, conv1w, conv1b, convw, convb);
    scan<<<NBLK, NTHR, SMEM_SZ>>>(fc1w, fc1b, bih, bhh, conv2w);
    final_out<<<(Bb*Ll)/256, 256>>>(x, mask, conv2w, conv2b, out);
}

// round 14
// speedup vs baseline: 1.2808x; 1.0071x over previous
#include <cuda_runtime.h>
#include <cuda_bf16.h>
#include <math.h>
#include <stdint.h>

typedef unsigned short ush;

#define Bb 256
#define Ll 512
#define Ff 28
#define NBLK 128
#define NTHR 256

#define BSTRIDE 552
#define ASTRIDE 136
#define BBYTES  (2*64*BSTRIDE*2)
#define ACHB    (2*64*ASTRIDE*2)   // 34816

#define OFF_B     0
#define OFF_A     141312
#define OFF_GATES (OFF_A+ACHB)
#define OFF_WAS   210944
#define OFF_BSUM  211200
#define OFF_CTXA  211456
#define OFF_SUA   211968
#define OFF_SBM   216064
#define OFF_QS    220160
#define OFF_SST   224256
#define SMEM_SZ   226304

__device__ __align__(16) ush g_wb[32*2*64*BSTRIDE];
__device__ __align__(16) ush g_hb[2*4*4*2*64*ASTRIDE];  // [parity][mt][chunk][half][64][136]
__device__ __align__(16) ush g_cb[4*2*64*ASTRIDE];      // [mt][half][64][136]
__device__ float g_xf[Ll*Bb*Ff];
__device__ float g_ua[Ll*Bb];
__device__ float g_bm[Ll*Bb];
__device__ float g_uab[Bb*Ll];
__device__ float g_bmb[Bb*Ll];
__device__ float g_wapart[Bb*32];
__device__ float g_fcpart[(size_t)Ll*Bb*32];
__device__ __align__(16) float g_pstat[2*512*4];        // [parity][l][mt] = partial D
__device__ unsigned g_leaf1[8*32];
__device__ unsigned g_root1;
__device__ volatile unsigned g_gen1;
__device__ unsigned g_mc1[4*32];
__device__ volatile unsigned g_mg1[4*32];
__device__ unsigned g_mc2[4*32];
__device__ volatile unsigned g_mg2[4*32];

#define BAR_ATT() asm volatile("bar.sync 1, 128;":::"memory")
#define BAR_GEM() asm volatile("bar.sync 2, 128;":::"memory")

__device__ __forceinline__ void gbar_arrive_wait(int blk){
    unsigned gen=g_gen1;
    __threadfence();
    if((atomicAdd(&g_leaf1[(blk&7)*32],1u)&15u)==15u){
        if((atomicAdd(&g_root1,1u)&7u)==7u){ __threadfence(); g_gen1=gen+1; }
    }
    while(g_gen1==gen){}
    __threadfence();
}
__device__ __forceinline__ void gbar_full(int blk){
    __threadfence();
    __syncthreads();
    if(threadIdx.x==0) gbar_arrive_wait(blk);
    __syncthreads();
}
__device__ __forceinline__ void gbarG(int blk){
    BAR_ATT();
    if(threadIdx.x==128) gbar_arrive_wait(blk);
    BAR_ATT();
}
__device__ __forceinline__ void mtbar_ctx(int mt){
    BAR_ATT();
    if(threadIdx.x==128){
        __threadfence();
        unsigned gen=g_mg1[mt*32];
        if((atomicAdd(&g_mc1[mt*32],1u)&31u)==31u){ __threadfence(); g_mg1[mt*32]=gen+1; }
        while(g_mg1[mt*32]==gen){}
        __threadfence();
    }
    BAR_ATT();
}
__device__ __forceinline__ void mtbar_end(int mt){
    __threadfence();
    __syncthreads();
    if(threadIdx.x==0){
        unsigned gen=g_mg2[mt*32];
        if((atomicAdd(&g_mc2[mt*32],1u)&31u)==31u){ __threadfence(); g_mg2[mt*32]=gen+1; }
        while(g_mg2[mt*32]==gen){}
        __threadfence();
    }
    __syncthreads();
}
__device__ __forceinline__ float sigm(float x){ return 1.f/(1.f+__expf(-x)); }
__device__ __forceinline__ int pos4(int km){ return 4*((km&7)>>1)+(km&1)+2*(km>>3); }
__device__ __forceinline__ uint32_t smem_u32(const void* p){
    uint32_t a; asm("{ .reg .u64 t; cvta.to.shared.u64 t, %1; cvt.u32.u64 %0, t; }":"=r"(a):"l"(p)); return a;
}
__device__ __forceinline__ void cpa16(uint32_t s, const void* g){
    asm volatile("cp.async.cg.shared.global [%0], [%1], 16;" :: "r"(s), "l"(g));
}
#define CP_COMMIT() asm volatile("cp.async.commit_group;":::"memory")
#define CP_WAIT(n)  asm volatile("cp.async.wait_group %0;"::"n"(n):"memory")

#define MMA(Cr,A0,A1,A2,A3,B0,B1) \
  asm volatile("mma.sync.aligned.m16n8k16.row.col.f32.bf16.bf16.f32 " \
    "{%0,%1,%2,%3},{%4,%5,%6,%7},{%8,%9},{%0,%1,%2,%3};" \
    : "+f"(Cr[0]),"+f"(Cr[1]),"+f"(Cr[2]),"+f"(Cr[3]) \
    : "r"(A0),"r"(A1),"r"(A2),"r"(A3),"r"(B0),"r"(B1))

__device__ __forceinline__ void bf16split(float v, ush& hi, ush& lo){
    __nv_bfloat16 h=__float2bfloat16(v);
    __nv_bfloat16 l=__float2bfloat16(v-__bfloat162float(h));
    hi=*(ush*)&h; lo=*(ush*)&l;
}

// GEMM-warp: warp mi covers rows mi*16..+16, all 64 N-cols
__device__ __forceinline__ void mma_chunk(const ush* smA, const ush* smB,
        int bK, int ktn, int mi, int lane, float (&C)[8][4]){
    const int r=lane>>2, c4=lane&3;
    const ush* aH = smA + (mi*16+r)*ASTRIDE + c4*4;
    const ush* aL = aH + 64*ASTRIDE;
    const ush* bB = smB + r*BSTRIDE + bK + c4*4;
    for(int kt=0; kt<ktn; kt++){
        int ka=kt*16;
        uint2 a0=*(const uint2*)(aH+ka);
        uint2 a1=*(const uint2*)(aH+8*ASTRIDE+ka);
        uint2 l0=*(const uint2*)(aL+ka);
        uint2 l1=*(const uint2*)(aL+8*ASTRIDE+ka);
        #pragma unroll
        for(int ni=0; ni<8; ni++){
            const ush* bp = bB + ni*8*BSTRIDE + ka;
            uint2 bh=*(const uint2*)bp;
            uint2 bl=*(const uint2*)(bp+64*BSTRIDE);
            MMA(C[ni], a0.x,a1.x,a0.y,a1.y, bh.x,bh.y);
            MMA(C[ni], a0.x,a1.x,a0.y,a1.y, bl.x,bl.y);
            MMA(C[ni], l0.x,l1.x,l0.y,l1.y, bh.x,bh.y);
        }
    }
}

__global__ void pack_w(const float* __restrict__ whh, const float* __restrict__ wih){
    int o=blockIdx.x*blockDim.x+threadIdx.x;
    if(o>=32*64*544) return;
    int nt=o/(64*544); int rem=o-nt*64*544; int j=rem/544; int k=rem%544;
    int row=(j&3)*512 + nt*16 + (j>>2);
    float v = (k<512) ? whh[(size_t)row*512+k] : ((k-512<Ff)? wih[row*Ff+(k-512)] : 0.f);
    ush hi,lo; bf16split(v,hi,lo);
    int pos=(k&~15) + pos4(k&15);
    size_t base=(size_t)nt*2*64*BSTRIDE;
    g_wb[base + (size_t)j*BSTRIDE + pos]=hi;
    g_wb[base + (size_t)64*BSTRIDE + (size_t)j*BSTRIDE + pos]=lo;
}
__global__ void zero_hb(){
    int i=blockIdx.x*blockDim.x+threadIdx.x;
    int nh=(int)(sizeof(g_hb)/16), nc=(int)(sizeof(g_cb)/16);
    if(i<nh) ((uint4*)g_hb)[i]=make_uint4(0,0,0,0);
    else if(i<nh+nc) ((uint4*)g_cb)[i-nh]=make_uint4(0,0,0,0);
}

__global__ void prep(const float* __restrict__ x, const float* __restrict__ mask,
                     const float* __restrict__ w1, const float* __restrict__ b1,
                     const float* __restrict__ cw, const float* __restrict__ cb){
    __shared__ float w1s[Ff*Ff*3];
    __shared__ float cws[Ff];
    for(int i=threadIdx.x;i<Ff*Ff*3;i+=blockDim.x) w1s[i]=w1[i];
    if(threadIdx.x<Ff) cws[threadIdx.x]=cw[threadIdx.x];
    __syncthreads();
    int gid=blockIdx.x*blockDim.x+threadIdx.x;
    int b=gid/Ll, l=gid%Ll;
    float m=mask[b*Ll+l];
    const float* xrow=x+(size_t)(b*Ll+l)*Ff;
    float accu=0.f;
    for(int fo=0;fo<Ff;fo++){
        float a=b1[fo];
        #pragma unroll
        for(int k=0;k<3;k++){
            int ll=l-1+k;
            if(ll>=0&&ll<Ll){
                const float* xp=x+(size_t)(b*Ll+ll)*Ff;
                const float* wp=w1s+fo*(Ff*3)+k;
                #pragma unroll 7
                for(int fi=0;fi<Ff;fi++) a+=xp[fi]*wp[fi*3];
            }
        }
        a*=m;
        a=(a>0.f)?a:(expf(a)-1.f);
        float xfv=a+xrow[fo];
        g_xf[(l*Bb+b)*Ff+fo]=xfv;
        accu+=xfv*cws[fo];
    }
    float ua=accu+cb[0], bm=1e9f*(m-1.f);
    g_ua[l*Bb+b]=ua; g_uab[b*Ll+l]=ua;
    g_bm[l*Bb+b]=bm; g_bmb[b*Ll+l]=bm;
}

__global__ void __launch_bounds__(NTHR,1) scan(
    const float* __restrict__ fc1w, const float* __restrict__ fc1b,
    const float* __restrict__ bih,  const float* __restrict__ bhh,
    const float* __restrict__ w2){

    extern __shared__ __align__(16) char sm[];
    ush*   smB   =(ush*)(sm+OFF_B);
    ush*   smA   =(ush*)(sm+OFF_A);
    float* gates =(float*)(sm+OFF_GATES);
    float* wa_s  =(float*)(sm+OFF_WAS);
    float* bsum_s=(float*)(sm+OFF_BSUM);
    float* ctxacc=(float*)(sm+OFF_CTXA);
    float* sua   =(float*)(sm+OFF_SUA);
    float* sbm   =(float*)(sm+OFF_SBM);
    float* q_s   =(float*)(sm+OFF_QS);
    float* sstat =(float*)(sm+OFF_SST);
    const uint32_t saA=smem_u32(sm)+OFF_A;

    const int tid=threadIdx.x, wid=tid>>5, lane=tid&31;
    const int blk=blockIdx.x, mt=blk>>5, nt=blk&31;
    const int gw=(wid<4);
    const int mi=wid&3;

    { const char* src=(const char*)&g_wb[(size_t)nt*2*64*BSTRIDE];
      uint32_t dB=smem_u32(sm)+OFF_B;
      for(int i=tid;i<BBYTES/16;i+=NTHR) cpa16(dB+i*16, src+(size_t)i*16);
      CP_COMMIT(); CP_WAIT(0); }
    if(tid<64){ int row=(tid&3)*512 + nt*16 + (tid>>2); bsum_s[tid]=bih[row]+bhh[row]; }
    for(int i=tid;i<16*64;i+=NTHR){
        int lo2=i>>6, b=i&63;
        sua[i]=g_ua[(nt*16+lo2)*Bb + mt*64+b];
        sbm[i]=g_bm[(nt*16+lo2)*Bb + mt*64+b];
    }
    for(int i=blk*NTHR+tid;i<Bb*32;i+=NBLK*NTHR) g_wapart[i]=0.f;

    const int prow=tid>>2, u0=(tid&3)*4;
    float f1v[4],w2v[4],cst[4];
    #pragma unroll
    for(int j=0;j<4;j++){ f1v[j]=fc1w[nt*16+u0+j]; w2v[j]=w2[nt*16+u0+j]; cst[j]=0.f; }
    const float f1b0=fc1b[0];
    const int chh=nt>>3;
    const size_t hP0=((((size_t)0*4+mt)*4+chh)*2*64 + prow)*ASTRIDE + (nt&7)*16;
    const size_t hP1=((((size_t)1*4+mt)*4+chh)*2*64 + prow)*ASTRIDE + (nt&7)*16;
    __syncthreads();
    gbar_full(blk);

    float C[8][4];
    for(int t=0;t<Ll;t++){
        const int rp=(t&1)^1;
        const int par=t&1;
        if(gw){
            // ===== GEMM lane =====
            #pragma unroll
            for(int a=0;a<8;a++){ C[a][0]=0.f;C[a][1]=0.f;C[a][2]=0.f;C[a][3]=0.f; }
            const char* base=(const char*)&g_hb[(((size_t)rp*4+mt)*4)*2*64*ASTRIDE];
            for(int i=tid;i<ACHB/16;i+=128) cpa16(saA+i*16, base+(size_t)i*16);
            CP_COMMIT();
            for(int i=tid;i<ACHB/16;i+=128) cpa16(saA+ACHB+i*16, base+(size_t)ACHB+(size_t)i*16);
            CP_COMMIT();
            for(int c=0;c<4;c++){
                if(c<3) CP_WAIT(1); else CP_WAIT(0);
                BAR_GEM();
                mma_chunk(smA+(c&1)*(ACHB/2), smB, c*128, 8, mi, lane, C);
                BAR_GEM();
                if(c<2){
                    const char* s2=base+(size_t)(c+2)*ACHB;
                    uint32_t dA=saA+(uint32_t)(c&1)*ACHB;
                    for(int i=tid;i<ACHB/16;i+=128) cpa16(dA+i*16, s2+(size_t)i*16);
                    CP_COMMIT();
                }
            }
        } else {
            // ===== Attention lane =====
            const int tid2=tid-128, aw=wid-4;
            // wa reduce over mt's 64 batches (2 threads per batch)
            { int bl=tid2>>1, q=tid2&1;
              const float4* wp=(const float4*)(g_wapart+(mt*64+bl)*32+q*16);
              float s=0.f;
              #pragma unroll
              for(int j2=0;j2<4;j2++){ float4 v=__ldcg(wp+j2); s+=v.x+v.y+v.z+v.w; }
              s+=__shfl_xor_sync(0xffffffffu,s,1);
              if(q==0) wa_s[bl]=s+f1b0;
            }
            BAR_ATT();
            // q precompute (own 2 batches, from L2 — pre-barrier, latency-tolerant)
            { int bloc=aw>>1, half=aw&1;
              int b=mt*64+nt*2+bloc;
              float wab=wa_s[nt*2+bloc];
              for(int lg=half*256; lg<half*256+256; lg+=32){
                  int lme=lg+lane;
                  float su=g_uab[b*Ll+lme]+wab;
                  su=(su>0.f)?su:0.01f*su; su+=g_bmb[b*Ll+lme];
                  q_s[bloc*512+lme]=__expf(su);
              } }
            // partial D: 16 l x 64 b, no max (scores are O(5))
            { int lsub=lane>>3, lloc=aw*4+lsub, bg=(lane&7)*8;
              float dd=0.f;
              #pragma unroll
              for(int j2=0;j2<8;j2++){
                  int b=bg+j2;
                  float s=sua[lloc*64+b]+wa_s[b];
                  s=(s>0.f)?s:0.01f*s; s+=sbm[lloc*64+b];
                  dd+=__expf(s);
              }
              dd+=__shfl_xor_sync(0xffffffffu,dd,1);
              dd+=__shfl_xor_sync(0xffffffffu,dd,2);
              dd+=__shfl_xor_sync(0xffffffffu,dd,4);
              if((lane&7)==0)
                  __stcg(&g_pstat[(par*512 + nt*16+lloc)*4 + mt], dd);
            }
            gbarG(blk);   // THE global barrier: D partials
            // merge pre-pass: sstat[l] = 1/sum (128 thr x 4 l, MLP)
            { const float4* ps=(const float4*)&g_pstat[par*512*4];
              #pragma unroll
              for(int j2=0;j2<4;j2++){
                  int l=tid2*4+j2;
                  float4 p=__ldcg(ps+l);
                  sstat[l]=__frcp_rn(p.x+p.y+p.z+p.w);
              } }
            BAR_ATT();
            // context: p = q*sstat (all LDS)
            { int bloc=aw>>1, half=aw&1;
              int b=mt*64+nt*2+bloc;
              float accf=0.f;
              for(int lg=half*256; lg<half*256+256; lg+=32){
                  int lme=lg+lane;
                  float p=q_s[bloc*512+lme]*sstat[lme];
                  #pragma unroll
                  for(int j2=0;j2<32;j2++){
                      float pj=__shfl_sync(0xffffffffu,p,j2);
                      if(lane<Ff) accf+=pj*g_xf[((lg+j2)*Bb+b)*Ff+lane];
                  }
              }
              if(lane<Ff) ctxacc[(bloc*2+half)*Ff+lane]=accf;
            }
            BAR_ATT();
            if(tid2<2*Ff){
                int bloc=tid2/Ff, f=tid2-bloc*Ff;
                float s=ctxacc[(bloc*2)*Ff+f]+ctxacc[(bloc*2+1)*Ff+f];
                int rowb=nt*2+bloc;
                int pos=(f&~15)+pos4(f&15);
                ush hi,lo; bf16split(s,hi,lo);
                size_t bmt=(size_t)mt*2*64*ASTRIDE;
                g_cb[bmt + (size_t)rowb*ASTRIDE + pos]=hi;
                g_cb[bmt + (size_t)(64+rowb)*ASTRIDE + pos]=lo;
            }
            mtbar_ctx(mt);
        }
        __syncthreads();   // join lanes

        // slim 8KB ctx copy into A buffer 0
        { const char* csrc=(const char*)&g_cb[(size_t)mt*2*64*ASTRIDE];
          for(int i=tid;i<512;i+=NTHR){
              int eoff=((i>>8)*64+((i>>2)&63))*ASTRIDE + (i&3)*8;
              cpa16(saA+(uint32_t)eoff*2, csrc+(size_t)eoff*2);
          }
          CP_COMMIT(); CP_WAIT(0); }
        __syncthreads();
        if(gw){
            mma_chunk(smA, smB, 512, 2, mi, lane, C);
            int r=lane>>2, c4=lane&3;
            #pragma unroll
            for(int ni=0;ni<8;ni++){
                int col=ni*8+c4*2;
                *(float2*)&gates[(mi*16+r)*68+col]  =make_float2(C[ni][0],C[ni][1]);
                *(float2*)&gates[(mi*16+r+8)*68+col]=make_float2(C[ni][2],C[ni][3]);
            }
        }
        __syncthreads();

        // ===== pointwise (all warps) =====
        ush* hb = g_hb + ((t&1)? hP1 : hP0);
        float swa=0.f, sfc=0.f;
        #pragma unroll
        for(int j=0;j<4;j++){
            int u=u0+j;
            float4 g4=*(float4*)&gates[prow*68+u*4];
            float gi=g4.x+bsum_s[u*4+0], gf=g4.y+bsum_s[u*4+1];
            float gg=g4.z+bsum_s[u*4+2], go=g4.w+bsum_s[u*4+3];
            float cn=sigm(gf)*cst[j]+sigm(gi)*tanhf(gg);
            float hn=sigm(go)*tanhf(cn);
            cst[j]=cn;
            swa+=hn*f1v[j]; sfc+=hn*w2v[j];
            ush hi,lo; bf16split(hn,hi,lo);
            int p4=pos4(u);
            hb[p4]=hi; hb[(size_t)64*ASTRIDE+p4]=lo;
        }
        swa+=__shfl_xor_sync(0xffffffffu,swa,1); swa+=__shfl_xor_sync(0xffffffffu,swa,2);
        sfc+=__shfl_xor_sync(0xffffffffu,sfc,1); sfc+=__shfl_xor_sync(0xffffffffu,sfc,2);
        if((tid&3)==0){
            int b=mt*64+prow;
            g_wapart[b*32+nt]=swa;
            g_fcpart[((size_t)t*Bb+b)*32+nt]=sfc;
        }
        mtbar_end(mt);
    }
}

__global__ void final_out(const float* __restrict__ x, const float* __restrict__ mask,
                          const float* __restrict__ w2, const float* __restrict__ b2,
                          float* __restrict__ out){
    __shared__ float w2s[Ff];
    if(threadIdx.x<Ff) w2s[threadIdx.x]=w2[512+threadIdx.x];
    __syncthreads();
    int gid=blockIdx.x*blockDim.x+threadIdx.x;
    int b=gid/Ll, l=gid%Ll;
    const float* fp=g_fcpart+(size_t)(l*Bb+b)*32;
    float s=0.f;
    #pragma unroll
    for(int j=0;j<32;j++) s+=fp[j];
    float m=mask[b*Ll+l];
    s*=m;
    const float* xr=x+(size_t)(b*Ll+l)*Ff;
    #pragma unroll 7
    for(int f=0;f<Ff;f++) s+=xr[f]*w2s[f];
    out[b*Ll+l]=(s+b2[0])*m;
}

extern "C" void kernel_launch(void* const* d_in, const int* in_sizes, int n_in,
                              void* d_out, int out_size){
    const float* x=(const float*)d_in[0];
    const float* mask=(const float*)d_in[1];
    const float* conv1w=(const float*)d_in[2];
    const float* conv1b=(const float*)d_in[3];
    const float* convw=(const float*)d_in[4];
    const float* convb=(const float*)d_in[5];
    const float* conv2w=(const float*)d_in[6];
    const float* conv2b=(const float*)d_in[7];
    const float* wih=(const float*)d_in[8];
    const float* whh=(const float*)d_in[9];
    const float* bih=(const float*)d_in[10];
    const float* bhh=(const float*)d_in[11];
    const float* fc1w=(const float*)d_in[12];
    const float* fc1b=(const float*)d_in[13];
    float* out=(float*)d_out;

    cudaFuncSetAttribute(scan, cudaFuncAttributeMaxDynamicSharedMemorySize, SMEM_SZ);
    pack_w<<<(32*64*544+255)/256, 256>>>(whh, wih);
    zero_hb<<<((int)((sizeof(g_hb)+sizeof(g_cb))/16)+255)/256, 256>>>();
    prep<<<(Bb*Ll)/256, 256>>>(x, mask, conv1w, conv1b, convw, convb);
    scan<<<NBLK, NTHR, SMEM_SZ>>>(fc1w, fc1b, bih, bhh, conv2w);
    final_out<<<(Bb*Ll)/256, 256>>>(x, mask, conv2w, conv2b, out);
}

// round 15
// speedup vs baseline: 1.6344x; 1.2760x over previous
#include <cuda_runtime.h>
#include <cuda_bf16.h>
#include <math.h>
#include <stdint.h>

typedef unsigned short ush;

#define Bb 256
#define Ll 512
#define Ff 28
#define NBLK 128
#define NTHR 256

#define BSTRIDE 552
#define ASTRIDE 136
#define BBYTES  (2*64*BSTRIDE*2)
#define ACHB    (2*64*ASTRIDE*2)   // 34816

#define OFF_B     0
#define OFF_A     141312
#define OFF_GATES (OFF_A+ACHB)
#define OFF_WAS   210944
#define OFF_BSUM  211200
#define OFF_CTXA  211456
#define OFF_SUA   211968
#define OFF_SBM   216064
#define OFF_QS    220160
#define OFF_SST   224256
#define SMEM_SZ   226304

__device__ __align__(16) ush g_wb[32*2*64*BSTRIDE];
__device__ __align__(16) ush g_hb[2*4*4*2*64*ASTRIDE];  // [parity][mt][chunk][half][64][136]
__device__ __align__(16) ush g_cb[4*2*64*ASTRIDE];      // [mt][half][64][136]
__device__ __align__(16) float g_xf[(size_t)Ll*Bb*32];  // [l][b][32] padded
__device__ float g_ua[Ll*Bb];
__device__ float g_bm[Ll*Bb];
__device__ float g_uab[Bb*Ll];
__device__ float g_bmb[Bb*Ll];
__device__ float g_wapart[Bb*32];
__device__ float g_fcpart[(size_t)Ll*Bb*32];
__device__ __align__(16) float g_pstat[2*512*4];        // [parity][l][mt] = partial D
__device__ unsigned g_leaf1[8*32];
__device__ unsigned g_root1;
__device__ volatile unsigned g_gen1;
__device__ unsigned g_mc1[4*32];
__device__ volatile unsigned g_mg1[4*32];
__device__ unsigned g_mc2[4*32];
__device__ volatile unsigned g_mg2[4*32];

#define BAR_ATT() asm volatile("bar.sync 1, 128;":::"memory")
#define BAR_GEM() asm volatile("bar.sync 2, 128;":::"memory")

__device__ __forceinline__ void gbar_arrive_wait(int blk){
    unsigned gen=g_gen1;
    __threadfence();
    if((atomicAdd(&g_leaf1[(blk&7)*32],1u)&15u)==15u){
        if((atomicAdd(&g_root1,1u)&7u)==7u){ __threadfence(); g_gen1=gen+1; }
    }
    while(g_gen1==gen){}
    __threadfence();
}
__device__ __forceinline__ void gbar_full(int blk){
    __threadfence();
    __syncthreads();
    if(threadIdx.x==0) gbar_arrive_wait(blk);
    __syncthreads();
}
__device__ __forceinline__ void gbarG(int blk){
    BAR_ATT();
    if(threadIdx.x==128) gbar_arrive_wait(blk);
    BAR_ATT();
}
__device__ __forceinline__ void mtbar_ctx(int mt){
    BAR_ATT();
    if(threadIdx.x==128){
        __threadfence();
        unsigned gen=g_mg1[mt*32];
        if((atomicAdd(&g_mc1[mt*32],1u)&31u)==31u){ __threadfence(); g_mg1[mt*32]=gen+1; }
        while(g_mg1[mt*32]==gen){}
        __threadfence();
    }
    BAR_ATT();
}
__device__ __forceinline__ void mtbar_end(int mt){
    __threadfence();
    __syncthreads();
    if(threadIdx.x==0){
        unsigned gen=g_mg2[mt*32];
        if((atomicAdd(&g_mc2[mt*32],1u)&31u)==31u){ __threadfence(); g_mg2[mt*32]=gen+1; }
        while(g_mg2[mt*32]==gen){}
        __threadfence();
    }
    __syncthreads();
}
__device__ __forceinline__ float sigm(float x){ return 1.f/(1.f+__expf(-x)); }
__device__ __forceinline__ int pos4(int km){ return 4*((km&7)>>1)+(km&1)+2*(km>>3); }
__device__ __forceinline__ uint32_t smem_u32(const void* p){
    uint32_t a; asm("{ .reg .u64 t; cvta.to.shared.u64 t, %1; cvt.u32.u64 %0, t; }":"=r"(a):"l"(p)); return a;
}
__device__ __forceinline__ void cpa16(uint32_t s, const void* g){
    asm volatile("cp.async.cg.shared.global [%0], [%1], 16;" :: "r"(s), "l"(g));
}
#define CP_COMMIT() asm volatile("cp.async.commit_group;":::"memory")
#define CP_WAIT(n)  asm volatile("cp.async.wait_group %0;"::"n"(n):"memory")

#define MMA(Cr,A0,A1,A2,A3,B0,B1) \
  asm volatile("mma.sync.aligned.m16n8k16.row.col.f32.bf16.bf16.f32 " \
    "{%0,%1,%2,%3},{%4,%5,%6,%7},{%8,%9},{%0,%1,%2,%3};" \
    : "+f"(Cr[0]),"+f"(Cr[1]),"+f"(Cr[2]),"+f"(Cr[3]) \
    : "r"(A0),"r"(A1),"r"(A2),"r"(A3),"r"(B0),"r"(B1))

__device__ __forceinline__ void bf16split(float v, ush& hi, ush& lo){
    __nv_bfloat16 h=__float2bfloat16(v);
    __nv_bfloat16 l=__float2bfloat16(v-__bfloat162float(h));
    hi=*(ush*)&h; lo=*(ush*)&l;
}

// GEMM-warp: warp mi covers rows mi*16..+16, all 64 N-cols
__device__ __forceinline__ void mma_chunk(const ush* smA, const ush* smB,
        int bK, int ktn, int mi, int lane, float (&C)[8][4]){
    const int r=lane>>2, c4=lane&3;
    const ush* aH = smA + (mi*16+r)*ASTRIDE + c4*4;
    const ush* aL = aH + 64*ASTRIDE;
    const ush* bB = smB + r*BSTRIDE + bK + c4*4;
    for(int kt=0; kt<ktn; kt++){
        int ka=kt*16;
        uint2 a0=*(const uint2*)(aH+ka);
        uint2 a1=*(const uint2*)(aH+8*ASTRIDE+ka);
        uint2 l0=*(const uint2*)(aL+ka);
        uint2 l1=*(const uint2*)(aL+8*ASTRIDE+ka);
        #pragma unroll
        for(int ni=0; ni<8; ni++){
            const ush* bp = bB + ni*8*BSTRIDE + ka;
            uint2 bh=*(const uint2*)bp;
            uint2 bl=*(const uint2*)(bp+64*BSTRIDE);
            MMA(C[ni], a0.x,a1.x,a0.y,a1.y, bh.x,bh.y);
            MMA(C[ni], a0.x,a1.x,a0.y,a1.y, bl.x,bl.y);
            MMA(C[ni], l0.x,l1.x,l0.y,l1.y, bh.x,bh.y);
        }
    }
}

__global__ void pack_w(const float* __restrict__ whh, const float* __restrict__ wih){
    int o=blockIdx.x*blockDim.x+threadIdx.x;
    if(o>=32*64*544) return;
    int nt=o/(64*544); int rem=o-nt*64*544; int j=rem/544; int k=rem%544;
    int row=(j&3)*512 + nt*16 + (j>>2);
    float v = (k<512) ? whh[(size_t)row*512+k] : ((k-512<Ff)? wih[row*Ff+(k-512)] : 0.f);
    ush hi,lo; bf16split(v,hi,lo);
    int pos=(k&~15) + pos4(k&15);
    size_t base=(size_t)nt*2*64*BSTRIDE;
    g_wb[base + (size_t)j*BSTRIDE + pos]=hi;
    g_wb[base + (size_t)64*BSTRIDE + (size_t)j*BSTRIDE + pos]=lo;
}
__global__ void zero_hb(){
    int i=blockIdx.x*blockDim.x+threadIdx.x;
    int nh=(int)(sizeof(g_hb)/16), nc=(int)(sizeof(g_cb)/16);
    if(i<nh) ((uint4*)g_hb)[i]=make_uint4(0,0,0,0);
    else if(i<nh+nc) ((uint4*)g_cb)[i-nh]=make_uint4(0,0,0,0);
}

__global__ void prep(const float* __restrict__ x, const float* __restrict__ mask,
                     const float* __restrict__ w1, const float* __restrict__ b1,
                     const float* __restrict__ cw, const float* __restrict__ cb){
    __shared__ float w1s[Ff*Ff*3];
    __shared__ float cws[Ff];
    for(int i=threadIdx.x;i<Ff*Ff*3;i+=blockDim.x) w1s[i]=w1[i];
    if(threadIdx.x<Ff) cws[threadIdx.x]=cw[threadIdx.x];
    __syncthreads();
    int gid=blockIdx.x*blockDim.x+threadIdx.x;
    int b=gid/Ll, l=gid%Ll;
    float m=mask[b*Ll+l];
    const float* xrow=x+(size_t)(b*Ll+l)*Ff;
    float accu=0.f;
    for(int fo=0;fo<Ff;fo++){
        float a=b1[fo];
        #pragma unroll
        for(int k=0;k<3;k++){
            int ll=l-1+k;
            if(ll>=0&&ll<Ll){
                const float* xp=x+(size_t)(b*Ll+ll)*Ff;
                const float* wp=w1s+fo*(Ff*3)+k;
                #pragma unroll 7
                for(int fi=0;fi<Ff;fi++) a+=xp[fi]*wp[fi*3];
            }
        }
        a*=m;
        a=(a>0.f)?a:(expf(a)-1.f);
        float xfv=a+xrow[fo];
        g_xf[((size_t)l*Bb+b)*32+fo]=xfv;
        accu+=xfv*cws[fo];
    }
    #pragma unroll
    for(int fo=Ff;fo<32;fo++) g_xf[((size_t)l*Bb+b)*32+fo]=0.f;
    float ua=accu+cb[0], bm=1e9f*(m-1.f);
    g_ua[l*Bb+b]=ua; g_uab[b*Ll+l]=ua;
    g_bm[l*Bb+b]=bm; g_bmb[b*Ll+l]=bm;
}

__global__ void __launch_bounds__(NTHR,1) scan(
    const float* __restrict__ fc1w, const float* __restrict__ fc1b,
    const float* __restrict__ bih,  const float* __restrict__ bhh,
    const float* __restrict__ w2){

    extern __shared__ __align__(16) char sm[];
    ush*   smB   =(ush*)(sm+OFF_B);
    ush*   smA   =(ush*)(sm+OFF_A);
    float* gates =(float*)(sm+OFF_GATES);
    float* wa_s  =(float*)(sm+OFF_WAS);
    float* bsum_s=(float*)(sm+OFF_BSUM);
    float* ctxacc=(float*)(sm+OFF_CTXA);
    float* sua   =(float*)(sm+OFF_SUA);
    float* sbm   =(float*)(sm+OFF_SBM);
    float* q_s   =(float*)(sm+OFF_QS);
    float* sstat =(float*)(sm+OFF_SST);
    const uint32_t saA=smem_u32(sm)+OFF_A;

    const int tid=threadIdx.x, wid=tid>>5, lane=tid&31;
    const int blk=blockIdx.x, mt=blk>>5, nt=blk&31;
    const int gw=(wid<4);
    const int mi=wid&3;

    { const char* src=(const char*)&g_wb[(size_t)nt*2*64*BSTRIDE];
      uint32_t dB=smem_u32(sm)+OFF_B;
      for(int i=tid;i<BBYTES/16;i+=NTHR) cpa16(dB+i*16, src+(size_t)i*16);
      CP_COMMIT(); CP_WAIT(0); }
    if(tid<64){ int row=(tid&3)*512 + nt*16 + (tid>>2); bsum_s[tid]=bih[row]+bhh[row]; }
    for(int i=tid;i<16*64;i+=NTHR){
        int lo2=i>>6, b=i&63;
        sua[i]=g_ua[(nt*16+lo2)*Bb + mt*64+b];
        sbm[i]=g_bm[(nt*16+lo2)*Bb + mt*64+b];
    }
    for(int i=blk*NTHR+tid;i<Bb*32;i+=NBLK*NTHR) g_wapart[i]=0.f;

    const int prow=tid>>2, u0=(tid&3)*4;
    float f1v[4],w2v[4],cst[4];
    #pragma unroll
    for(int j=0;j<4;j++){ f1v[j]=fc1w[nt*16+u0+j]; w2v[j]=w2[nt*16+u0+j]; cst[j]=0.f; }
    const float f1b0=fc1b[0];
    const int chh=nt>>3;
    const size_t hP0=((((size_t)0*4+mt)*4+chh)*2*64 + prow)*ASTRIDE + (nt&7)*16;
    const size_t hP1=((((size_t)1*4+mt)*4+chh)*2*64 + prow)*ASTRIDE + (nt&7)*16;
    __syncthreads();
    gbar_full(blk);

    float C[8][4];
    for(int t=0;t<Ll;t++){
        const int rp=(t&1)^1;
        const int par=t&1;
        if(gw){
            // ===== GEMM lane =====
            #pragma unroll
            for(int a=0;a<8;a++){ C[a][0]=0.f;C[a][1]=0.f;C[a][2]=0.f;C[a][3]=0.f; }
            const char* base=(const char*)&g_hb[(((size_t)rp*4+mt)*4)*2*64*ASTRIDE];
            for(int i=tid;i<ACHB/16;i+=128) cpa16(saA+i*16, base+(size_t)i*16);
            CP_COMMIT();
            for(int i=tid;i<ACHB/16;i+=128) cpa16(saA+ACHB+i*16, base+(size_t)ACHB+(size_t)i*16);
            CP_COMMIT();
            for(int c=0;c<4;c++){
                if(c<3) CP_WAIT(1); else CP_WAIT(0);
                BAR_GEM();
                mma_chunk(smA+(c&1)*(ACHB/2), smB, c*128, 8, mi, lane, C);
                BAR_GEM();
                if(c<2){
                    const char* s2=base+(size_t)(c+2)*ACHB;
                    uint32_t dA=saA+(uint32_t)(c&1)*ACHB;
                    for(int i=tid;i<ACHB/16;i+=128) cpa16(dA+i*16, s2+(size_t)i*16);
                    CP_COMMIT();
                }
            }
        } else {
            // ===== Attention lane =====
            const int tid2=tid-128, aw=wid-4;
            // wa reduce over mt's 64 batches (2 threads per batch)
            { int bl=tid2>>1, q=tid2&1;
              const float4* wp=(const float4*)(g_wapart+(mt*64+bl)*32+q*16);
              float s=0.f;
              #pragma unroll
              for(int j2=0;j2<4;j2++){ float4 v=__ldcg(wp+j2); s+=v.x+v.y+v.z+v.w; }
              s+=__shfl_xor_sync(0xffffffffu,s,1);
              if(q==0) wa_s[bl]=s+f1b0;
            }
            BAR_ATT();
            // q precompute (own 2 batches, from L2 — pre-barrier, latency-tolerant)
            { int bloc=aw>>1, half=aw&1;
              int b=mt*64+nt*2+bloc;
              float wab=wa_s[nt*2+bloc];
              for(int lg=half*256; lg<half*256+256; lg+=32){
                  int lme=lg+lane;
                  float su=g_uab[b*Ll+lme]+wab;
                  su=(su>0.f)?su:0.01f*su; su+=g_bmb[b*Ll+lme];
                  q_s[bloc*512+lme]=__expf(su);
              } }
            // partial D: 16 l x 64 b, no max (scores are O(5))
            { int lsub=lane>>3, lloc=aw*4+lsub, bg=(lane&7)*8;
              float dd=0.f;
              #pragma unroll
              for(int j2=0;j2<8;j2++){
                  int b=bg+j2;
                  float s=sua[lloc*64+b]+wa_s[b];
                  s=(s>0.f)?s:0.01f*s; s+=sbm[lloc*64+b];
                  dd+=__expf(s);
              }
              dd+=__shfl_xor_sync(0xffffffffu,dd,1);
              dd+=__shfl_xor_sync(0xffffffffu,dd,2);
              dd+=__shfl_xor_sync(0xffffffffu,dd,4);
              if((lane&7)==0)
                  __stcg(&g_pstat[(par*512 + nt*16+lloc)*4 + mt], dd);
            }
            gbarG(blk);   // THE global barrier: D partials
            // merge pre-pass: sstat[l] = 1/sum (128 thr x 4 l, MLP)
            { const float4* ps=(const float4*)&g_pstat[par*512*4];
              #pragma unroll
              for(int j2=0;j2<4;j2++){
                  int l=tid2*4+j2;
                  float4 p=__ldcg(ps+l);
                  sstat[l]=__frcp_rn(p.x+p.y+p.z+p.w);
              } }
            BAR_ATT();
            // context: vectorized — 4 l per LDG.128, no shfl broadcast
            { int bloc=aw>>1, half=aw&1;
              int b=mt*64+nt*2+bloc;
              int ls=lane>>3, f4=lane&7;
              const float4* xfp=(const float4*)g_xf;
              float4 acc4=make_float4(0.f,0.f,0.f,0.f);
              for(int lg=half*256; lg<half*256+256; lg+=4){
                  int lme=lg+ls;
                  float p=q_s[bloc*512+lme]*sstat[lme];
                  float4 v=__ldcg(&xfp[((size_t)lme*Bb+b)*8+f4]);
                  acc4.x+=p*v.x; acc4.y+=p*v.y; acc4.z+=p*v.z; acc4.w+=p*v.w;
              }
              acc4.x+=__shfl_xor_sync(0xffffffffu,acc4.x,8);
              acc4.y+=__shfl_xor_sync(0xffffffffu,acc4.y,8);
              acc4.z+=__shfl_xor_sync(0xffffffffu,acc4.z,8);
              acc4.w+=__shfl_xor_sync(0xffffffffu,acc4.w,8);
              acc4.x+=__shfl_xor_sync(0xffffffffu,acc4.x,16);
              acc4.y+=__shfl_xor_sync(0xffffffffu,acc4.y,16);
              acc4.z+=__shfl_xor_sync(0xffffffffu,acc4.z,16);
              acc4.w+=__shfl_xor_sync(0xffffffffu,acc4.w,16);
              if(lane<8) *(float4*)&ctxacc[(bloc*2+half)*32+lane*4]=acc4;
            }
            BAR_ATT();
            if(tid2<64){
                int bloc=tid2>>5, f=tid2&31;
                float s=ctxacc[(bloc*2)*32+f]+ctxacc[(bloc*2+1)*32+f];
                int rowb=nt*2+bloc;
                int pos=(f&~15)+pos4(f&15);
                ush hi,lo; bf16split(s,hi,lo);
                size_t bmt=(size_t)mt*2*64*ASTRIDE;
                g_cb[bmt + (size_t)rowb*ASTRIDE + pos]=hi;
                g_cb[bmt + (size_t)(64+rowb)*ASTRIDE + pos]=lo;
            }
            mtbar_ctx(mt);
        }
        __syncthreads();   // join lanes

        // slim 8KB ctx copy into A buffer 0
        { const char* csrc=(const char*)&g_cb[(size_t)mt*2*64*ASTRIDE];
          for(int i=tid;i<512;i+=NTHR){
              int eoff=((i>>8)*64+((i>>2)&63))*ASTRIDE + (i&3)*8;
              cpa16(saA+(uint32_t)eoff*2, csrc+(size_t)eoff*2);
          }
          CP_COMMIT(); CP_WAIT(0); }
        __syncthreads();
        if(gw){
            mma_chunk(smA, smB, 512, 2, mi, lane, C);
            int r=lane>>2, c4=lane&3;
            #pragma unroll
            for(int ni=0;ni<8;ni++){
                int col=ni*8+c4*2;
                *(float2*)&gates[(mi*16+r)*68+col]  =make_float2(C[ni][0],C[ni][1]);
                *(float2*)&gates[(mi*16+r+8)*68+col]=make_float2(C[ni][2],C[ni][3]);
            }
        }
        __syncthreads();

        // ===== pointwise (all warps) =====
        ush* hb = g_hb + ((t&1)? hP1 : hP0);
        float swa=0.f, sfc=0.f;
        #pragma unroll
        for(int j=0;j<4;j++){
            int u=u0+j;
            float4 g4=*(float4*)&gates[prow*68+u*4];
            float gi=g4.x+bsum_s[u*4+0], gf=g4.y+bsum_s[u*4+1];
            float gg=g4.z+bsum_s[u*4+2], go=g4.w+bsum_s[u*4+3];
            float cn=sigm(gf)*cst[j]+sigm(gi)*tanhf(gg);
            float hn=sigm(go)*tanhf(cn);
            cst[j]=cn;
            swa+=hn*f1v[j]; sfc+=hn*w2v[j];
            ush hi,lo; bf16split(hn,hi,lo);
            int p4=pos4(u);
            hb[p4]=hi; hb[(size_t)64*ASTRIDE+p4]=lo;
        }
        swa+=__shfl_xor_sync(0xffffffffu,swa,1); swa+=__shfl_xor_sync(0xffffffffu,swa,2);
        sfc+=__shfl_xor_sync(0xffffffffu,sfc,1); sfc+=__shfl_xor_sync(0xffffffffu,sfc,2);
        if((tid&3)==0){
            int b=mt*64+prow;
            g_wapart[b*32+nt]=swa;
            g_fcpart[((size_t)t*Bb+b)*32+nt]=sfc;
        }
        mtbar_end(mt);
    }
}

__global__ void final_out(const float* __restrict__ x, const float* __restrict__ mask,
                          const float* __restrict__ w2, const float* __restrict__ b2,
                          float* __restrict__ out){
    __shared__ float w2s[Ff];
    if(threadIdx.x<Ff) w2s[threadIdx.x]=w2[512+threadIdx.x];
    __syncthreads();
    int gid=blockIdx.x*blockDim.x+threadIdx.x;
    int b=gid/Ll, l=gid%Ll;
    const float* fp=g_fcpart+(size_t)(l*Bb+b)*32;
    float s=0.f;
    #pragma unroll
    for(int j=0;j<32;j++) s+=fp[j];
    float m=mask[b*Ll+l];
    s*=m;
    const float* xr=x+(size_t)(b*Ll+l)*Ff;
    #pragma unroll 7
    for(int f=0;f<Ff;f++) s+=xr[f]*w2s[f];
    out[b*Ll+l]=(s+b2[0])*m;
}

extern "C" void kernel_launch(void* const* d_in, const int* in_sizes, int n_in,
                              void* d_out, int out_size){
    const float* x=(const float*)d_in[0];
    const float* mask=(const float*)d_in[1];
    const float* conv1w=(const float*)d_in[2];
    const float* conv1b=(const float*)d_in[3];
    const float* convw=(const float*)d_in[4];
    const float* convb=(const float*)d_in[5];
    const float* conv2w=(const float*)d_in[6];
    const float* conv2b=(const float*)d_in[7];
    const float* wih=(const float*)d_in[8];
    const float* whh=(const float*)d_in[9];
    const float* bih=(const float*)d_in[10];
    const float* bhh=(const float*)d_in[11];
    const float* fc1w=(const float*)d_in[12];
    const float* fc1b=(const float*)d_in[13];
    float* out=(float*)d_out;

    cudaFuncSetAttribute(scan, cudaFuncAttributeMaxDynamicSharedMemorySize, SMEM_SZ);
    pack_w<<<(32*64*544+255)/256, 256>>>(whh, wih);
    zero_hb<<<((int)((sizeof(g_hb)+sizeof(g_cb))/16)+255)/256, 256>>>();
    prep<<<(Bb*Ll)/256, 256>>>(x, mask, conv1w, conv1b, convw, convb);
    scan<<<NBLK, NTHR, SMEM_SZ>>>(fc1w, fc1b, bih, bhh, conv2w);
    final_out<<<(Bb*Ll)/256, 256>>>(x, mask, conv2w, conv2b, out);
}